// round 1
// baseline (speedup 1.0000x reference)
#include <cuda_runtime.h>
#include <math.h>

#define NB 8
#define NL 8192
#define NC 512
#define NH 16
#define NS 128          // L-slices for stats partial reduction
#define LS (NL/NS)      // 64 rows per slice

// ---- scratch (no allocations allowed) ----
__device__ float g_part[NB*NS*3*NC];   // [b][s][comp:{sumabs,max,sumsq}][c]  (6 MB)
__device__ float g_q [NB*NC*NH];
__device__ float g_k [NB*NC*NH];
__device__ float g_gg[NB*NC*NH];       // h_graph_in
__device__ float g_hl[NB*NC*NH];       // h_local
__device__ float g_prior[NC*NC];       // relu(E E^T)  (1 MB)

// ============================================================
// Kernel 1: streaming stats over L.  grid (NS, NB), 128 threads.
// Each thread owns a float4 column group, loops LS rows.
// ============================================================
__global__ void __launch_bounds__(128) stats_partial(const float* __restrict__ r) {
    int s = blockIdx.x, b = blockIdx.y;
    int t = threadIdx.x;                       // 0..127 -> c = 4t
    const float* base = r + ((size_t)b*NL + (size_t)s*LS)*NC + t*4;
    float4 s1 = make_float4(0.f,0.f,0.f,0.f);
    float4 s2 = make_float4(0.f,0.f,0.f,0.f);
    float4 mx = make_float4(0.f,0.f,0.f,0.f);
    #pragma unroll 8
    for (int l = 0; l < LS; l++) {
        float4 v = __ldg((const float4*)(base + (size_t)l*NC));
        float ax = fabsf(v.x), ay = fabsf(v.y), az = fabsf(v.z), aw = fabsf(v.w);
        s1.x += ax; s1.y += ay; s1.z += az; s1.w += aw;
        s2.x += v.x*v.x; s2.y += v.y*v.y; s2.z += v.z*v.z; s2.w += v.w*v.w;
        mx.x = fmaxf(mx.x, ax); mx.y = fmaxf(mx.y, ay);
        mx.z = fmaxf(mx.z, az); mx.w = fmaxf(mx.w, aw);
    }
    size_t o = (size_t)((b*NS + s)*3)*NC + t*4;
    *(float4*)(g_part + o         ) = s1;
    *(float4*)(g_part + o +   NC  ) = mx;
    *(float4*)(g_part + o + 2*NC  ) = s2;
}

// ============================================================
// Kernel 2: combine partials (fixed order -> deterministic),
// compute h0 and all small per-(b,c) MLPs.
// grid (4, NB), 128 threads; thread handles one c.
// ============================================================
__global__ void __launch_bounds__(128) stats_final(
    const float* __restrict__ Wl1, const float* __restrict__ bl1,
    const float* __restrict__ Wl2, const float* __restrict__ bl2,
    const float* __restrict__ Wg,  const float* __restrict__ bg,
    const float* __restrict__ Wq,  const float* __restrict__ bq,
    const float* __restrict__ Wk,  const float* __restrict__ bk,
    float* __restrict__ h0_out)
{
    int b = blockIdx.y;
    int c = blockIdx.x*128 + threadIdx.x;
    int t = threadIdx.x;

    __shared__ float sWl1[64], sWl2[256], sWg[64], sWq[64], sWk[64];
    __shared__ float sbl1[16], sbl2[16], sbg[16], sbq[16], sbk[16];
    if (t < 64) { sWl1[t]=Wl1[t]; sWg[t]=Wg[t]; sWq[t]=Wq[t]; sWk[t]=Wk[t]; }
    if (t >= 64 && t < 80) {
        int i = t-64;
        sbl1[i]=bl1[i]; sbl2[i]=bl2[i]; sbg[i]=bg[i]; sbq[i]=bq[i]; sbk[i]=bk[i];
    }
    sWl2[t] = Wl2[t]; sWl2[t+128] = Wl2[t+128];
    __syncthreads();

    float s1 = 0.f, s2 = 0.f, mx = 0.f;
    for (int s = 0; s < NS; s++) {
        size_t o = (size_t)((b*NS + s)*3)*NC + c;
        s1 += g_part[o];
        mx  = fmaxf(mx, g_part[o + NC]);
        s2 += g_part[o + 2*NC];
    }
    float m  = s1 * (1.f/NL);
    float sq = s2 * (1.f/NL);
    float sd = sqrtf(fmaxf(sq - m*m, 0.f));
    float h0[4] = { m, mx, sd, sq };
    *(float4*)(h0_out + ((size_t)b*NC + c)*4) = make_float4(m, mx, sd, sq);

    // local branch hidden = relu(W_l1 h0 + b_l1)
    float hid[16];
    #pragma unroll
    for (int i = 0; i < 16; i++) {
        float a = sbl1[i];
        #pragma unroll
        for (int j = 0; j < 4; j++) a += sWl1[i*4+j]*h0[j];
        hid[i] = fmaxf(a, 0.f);
    }
    size_t ofs = ((size_t)b*NC + c)*NH;
    #pragma unroll
    for (int i = 0; i < 16; i++) {
        float a = sbl2[i];
        #pragma unroll
        for (int j = 0; j < 16; j++) a += sWl2[i*16+j]*hid[j];
        g_hl[ofs+i] = a;
        float qv = sbq[i], kv = sbk[i], gv = sbg[i];
        #pragma unroll
        for (int j = 0; j < 4; j++) {
            qv += sWq[i*4+j]*h0[j];
            kv += sWk[i*4+j]*h0[j];
            gv += sWg[i*4+j]*h0[j];
        }
        g_q[ofs+i] = qv; g_k[ofs+i] = kv; g_gg[ofs+i] = gv;
    }
}

// ============================================================
// Kernel 3: sim_prior = relu(E E^T).  grid (NC), 128 threads.
// ============================================================
__global__ void __launch_bounds__(128) prior_kernel(const float* __restrict__ E) {
    int c = blockIdx.x;
    __shared__ float ec[16];
    if (threadIdx.x < 16) ec[threadIdx.x] = E[c*16 + threadIdx.x];
    __syncthreads();
    for (int d = threadIdx.x; d < NC; d += blockDim.x) {
        const float* ed = E + d*16;
        float s = 0.f;
        #pragma unroll
        for (int j = 0; j < 16; j++) s += ec[j]*ed[j];
        g_prior[(size_t)c*NC + d] = fmaxf(s, 0.f);
    }
}

// ============================================================
// Kernel 4: per (b,c) row: sim, softmax, write A, msg GEMV, epilogue.
// grid (NC, NB), 256 threads.
// ============================================================
__global__ void __launch_bounds__(256) row_kernel(
    const float* __restrict__ Wf, const float* __restrict__ bf,
    const float* __restrict__ Wo, const float* __restrict__ bo,
    const float* __restrict__ lng, const float* __restrict__ lnb,
    float* __restrict__ out_alpha, float* __restrict__ out_A)
{
    int c = blockIdx.x, b = blockIdx.y;
    int t = threadIdx.x;
    int lane = t & 31, warp = t >> 5;

    __shared__ float sh_q[16];
    __shared__ float sh_r[128];
    __shared__ float sh_msg[16];
    __shared__ float sh_s[2];

    if (t < 16) sh_q[t] = g_q[((size_t)b*NC + c)*NH + t];
    __syncthreads();
    float q[16];
    #pragma unroll
    for (int j = 0; j < 16; j++) q[j] = sh_q[j];

    // --- sim row (2 values per thread) ---
    float sv[2];
    #pragma unroll
    for (int i = 0; i < 2; i++) {
        int d = t + i*256;
        const float4* kp = (const float4*)(g_k + ((size_t)b*NC + d)*NH);
        float4 k0 = __ldg(kp), k1 = __ldg(kp+1), k2 = __ldg(kp+2), k3 = __ldg(kp+3);
        float dot = q[0]*k0.x + q[1]*k0.y + q[2]*k0.z + q[3]*k0.w
                  + q[4]*k1.x + q[5]*k1.y + q[6]*k1.z + q[7]*k1.w
                  + q[8]*k2.x + q[9]*k2.y + q[10]*k2.z + q[11]*k2.w
                  + q[12]*k3.x + q[13]*k3.y + q[14]*k3.z + q[15]*k3.w;
        float s = fmaxf(dot, 0.f) + 0.2f*__ldg(g_prior + (size_t)c*NC + d);
        if (d == c) s += 1.f;
        sv[i] = s;
    }

    // --- max reduce ---
    float mloc = fmaxf(sv[0], sv[1]);
    #pragma unroll
    for (int off = 16; off; off >>= 1)
        mloc = fmaxf(mloc, __shfl_xor_sync(0xffffffffu, mloc, off));
    if (lane == 0) sh_r[warp] = mloc;
    __syncthreads();
    if (t == 0) {
        float mm = sh_r[0];
        #pragma unroll
        for (int w = 1; w < 8; w++) mm = fmaxf(mm, sh_r[w]);
        sh_s[0] = mm;
    }
    __syncthreads();
    float mxv = sh_s[0];

    // --- exp + sum reduce ---
    float e0 = __expf(sv[0] - mxv);
    float e1 = __expf(sv[1] - mxv);
    float sloc = e0 + e1;
    #pragma unroll
    for (int off = 16; off; off >>= 1)
        sloc += __shfl_xor_sync(0xffffffffu, sloc, off);
    if (lane == 0) sh_r[warp] = sloc;
    __syncthreads();
    if (t == 0) {
        float ss = 0.f;
        #pragma unroll
        for (int w = 0; w < 8; w++) ss += sh_r[w];
        sh_s[1] = ss;
    }
    __syncthreads();
    float inv = __frcp_rn(sh_s[1]);

    // --- write A row + accumulate msg = A_row @ g ---
    float acc[16];
    #pragma unroll
    for (int j = 0; j < 16; j++) acc[j] = 0.f;
    float* Arow = out_A + ((size_t)b*NC + c)*NC;
    float ev[2] = { e0, e1 };
    #pragma unroll
    for (int i = 0; i < 2; i++) {
        int d = t + i*256;
        float a = ev[i]*inv;
        Arow[d] = a;
        const float4* gp = (const float4*)(g_gg + ((size_t)b*NC + d)*NH);
        float4 g0 = __ldg(gp), g1 = __ldg(gp+1), g2 = __ldg(gp+2), g3 = __ldg(gp+3);
        acc[0]+=a*g0.x; acc[1]+=a*g0.y; acc[2]+=a*g0.z; acc[3]+=a*g0.w;
        acc[4]+=a*g1.x; acc[5]+=a*g1.y; acc[6]+=a*g1.z; acc[7]+=a*g1.w;
        acc[8]+=a*g2.x; acc[9]+=a*g2.y; acc[10]+=a*g2.z; acc[11]+=a*g2.w;
        acc[12]+=a*g3.x; acc[13]+=a*g3.y; acc[14]+=a*g3.z; acc[15]+=a*g3.w;
    }
    #pragma unroll
    for (int off = 16; off; off >>= 1) {
        #pragma unroll
        for (int j = 0; j < 16; j++)
            acc[j] += __shfl_xor_sync(0xffffffffu, acc[j], off);
    }
    if (lane == 0) {
        #pragma unroll
        for (int j = 0; j < 16; j++) sh_r[warp*16 + j] = acc[j];
    }
    __syncthreads();
    if (t < 16) {
        float v = 0.f;
        #pragma unroll
        for (int w = 0; w < 8; w++) v += sh_r[w*16 + t];
        sh_msg[t] = v;
    }
    __syncthreads();

    // --- epilogue: fusion + LN + W_f + W_o + tanh ---
    if (t == 0) {
        const float* gp = g_gg + ((size_t)b*NC + c)*NH;
        const float* hp = g_hl + ((size_t)b*NC + c)*NH;
        float h[16]; float musum = 0.f;
        #pragma unroll
        for (int j = 0; j < 16; j++) {
            float hg = gp[j] + 0.3f*fmaxf(sh_msg[j], 0.f);
            h[j] = hp[j] + 0.1f*hg;
            musum += h[j];
        }
        float mu = musum * (1.f/16.f);
        float var = 0.f;
        #pragma unroll
        for (int j = 0; j < 16; j++) { float dd = h[j]-mu; var += dd*dd; }
        var *= (1.f/16.f);
        float rinv = rsqrtf(var + 1e-5f);
        float hn[16];
        #pragma unroll
        for (int j = 0; j < 16; j++) hn[j] = (h[j]-mu)*rinv*lng[j] + lnb[j];
        float o = bo[0];
        #pragma unroll
        for (int i = 0; i < 16; i++) {
            float a2 = bf[i];
            #pragma unroll
            for (int j = 0; j < 16; j++) a2 += Wf[i*16+j]*hn[j];
            o += Wo[i]*fmaxf(a2, 0.f);
        }
        out_alpha[(size_t)b*NC + c] = 1.2f + 0.3f*tanhf(o);
    }
}

// ============================================================
extern "C" void kernel_launch(void* const* d_in, const int* in_sizes, int n_in,
                              void* d_out, int out_size)
{
    const float* res = (const float*)d_in[0];
    const float* emb = (const float*)d_in[1];
    const float* Wl1 = (const float*)d_in[2];
    const float* bl1 = (const float*)d_in[3];
    const float* Wl2 = (const float*)d_in[4];
    const float* bl2 = (const float*)d_in[5];
    const float* Wg  = (const float*)d_in[6];
    const float* bg  = (const float*)d_in[7];
    const float* Wq  = (const float*)d_in[8];
    const float* bq  = (const float*)d_in[9];
    const float* Wk  = (const float*)d_in[10];
    const float* bk  = (const float*)d_in[11];
    const float* Wf  = (const float*)d_in[12];
    const float* bf  = (const float*)d_in[13];
    const float* Wo  = (const float*)d_in[14];
    const float* bo  = (const float*)d_in[15];
    const float* lng = (const float*)d_in[16];
    const float* lnb = (const float*)d_in[17];

    float* out       = (float*)d_out;
    float* out_alpha = out;                       // [B,1,C]   = 4096
    float* out_h0    = out + NB*NC;               // [B,C,4]   = 16384
    float* out_A     = out + NB*NC + NB*NC*4;     // [B,C,C]   = 2097152

    prior_kernel <<<NC, 128>>>(emb);
    stats_partial<<<dim3(NS, NB), 128>>>(res);
    stats_final  <<<dim3(4, NB), 128>>>(Wl1,bl1,Wl2,bl2,Wg,bg,Wq,bq,Wk,bk,out_h0);
    row_kernel   <<<dim3(NC, NB), 256>>>(Wf,bf,Wo,bo,lng,lnb,out_alpha,out_A);
}

// round 5
// speedup vs baseline: 1.3404x; 1.3404x over previous
#include <cuda_runtime.h>
#include <math.h>

#define NB 8
#define NL 8192
#define NC 512
#define NH 16
#define NS 128          // L-slices for stats partial reduction
#define LS (NL/NS)      // 64 rows per slice

// ---- scratch (no allocations allowed) ----
__device__ float g_part[NB*NS*3*NC];   // [b][s][comp:{sumabs,max,sumsq}][c]  (6 MB)
__device__ float g_q [NB*NC*NH];
__device__ float g_k [NB*NC*NH];
__device__ float g_gg[NB*NC*NH];       // h_graph_in
__device__ float g_hl[NB*NC*NH];       // h_local
__device__ float g_prior[NC*NC];       // relu(E E^T)  (1 MB)

// ============================================================
// Kernel 1: streaming stats over L.  grid (NS, NB), 128 threads.
// ============================================================
__global__ void __launch_bounds__(128) stats_partial(const float* __restrict__ r) {
    int s = blockIdx.x, b = blockIdx.y;
    int t = threadIdx.x;
    const float* base = r + ((size_t)b*NL + (size_t)s*LS)*NC + t*4;
    float4 s1 = make_float4(0.f,0.f,0.f,0.f);
    float4 s2 = make_float4(0.f,0.f,0.f,0.f);
    float4 mx = make_float4(0.f,0.f,0.f,0.f);
    #pragma unroll 8
    for (int l = 0; l < LS; l++) {
        float4 v = __ldg((const float4*)(base + (size_t)l*NC));
        float ax = fabsf(v.x), ay = fabsf(v.y), az = fabsf(v.z), aw = fabsf(v.w);
        s1.x += ax; s1.y += ay; s1.z += az; s1.w += aw;
        s2.x += v.x*v.x; s2.y += v.y*v.y; s2.z += v.z*v.z; s2.w += v.w*v.w;
        mx.x = fmaxf(mx.x, ax); mx.y = fmaxf(mx.y, ay);
        mx.z = fmaxf(mx.z, az); mx.w = fmaxf(mx.w, aw);
    }
    size_t o = (size_t)((b*NS + s)*3)*NC + t*4;
    *(float4*)(g_part + o         ) = s1;
    *(float4*)(g_part + o +   NC  ) = mx;
    *(float4*)(g_part + o + 2*NC  ) = s2;
}

// ============================================================
// Kernel 2: combine partials, compute h0 + small per-(b,c) MLPs.
// ============================================================
__global__ void __launch_bounds__(128) stats_final(
    const float* __restrict__ Wl1, const float* __restrict__ bl1,
    const float* __restrict__ Wl2, const float* __restrict__ bl2,
    const float* __restrict__ Wg,  const float* __restrict__ bg,
    const float* __restrict__ Wq,  const float* __restrict__ bq,
    const float* __restrict__ Wk,  const float* __restrict__ bk,
    float* __restrict__ h0_out)
{
    int b = blockIdx.y;
    int c = blockIdx.x*128 + threadIdx.x;
    int t = threadIdx.x;

    __shared__ float sWl1[64], sWl2[256], sWg[64], sWq[64], sWk[64];
    __shared__ float sbl1[16], sbl2[16], sbg[16], sbq[16], sbk[16];
    if (t < 64) { sWl1[t]=Wl1[t]; sWg[t]=Wg[t]; sWq[t]=Wq[t]; sWk[t]=Wk[t]; }
    if (t >= 64 && t < 80) {
        int i = t-64;
        sbl1[i]=bl1[i]; sbl2[i]=bl2[i]; sbg[i]=bg[i]; sbq[i]=bq[i]; sbk[i]=bk[i];
    }
    sWl2[t] = Wl2[t]; sWl2[t+128] = Wl2[t+128];
    __syncthreads();

    float s1 = 0.f, s2 = 0.f, mx = 0.f;
    for (int s = 0; s < NS; s++) {
        size_t o = (size_t)((b*NS + s)*3)*NC + c;
        s1 += g_part[o];
        mx  = fmaxf(mx, g_part[o + NC]);
        s2 += g_part[o + 2*NC];
    }
    float m  = s1 * (1.f/NL);
    float sq = s2 * (1.f/NL);
    float sd = sqrtf(fmaxf(sq - m*m, 0.f));
    float h0[4] = { m, mx, sd, sq };
    *(float4*)(h0_out + ((size_t)b*NC + c)*4) = make_float4(m, mx, sd, sq);

    float hid[16];
    #pragma unroll
    for (int i = 0; i < 16; i++) {
        float a = sbl1[i];
        #pragma unroll
        for (int j = 0; j < 4; j++) a += sWl1[i*4+j]*h0[j];
        hid[i] = fmaxf(a, 0.f);
    }
    size_t ofs = ((size_t)b*NC + c)*NH;
    #pragma unroll
    for (int i = 0; i < 16; i++) {
        float a = sbl2[i];
        #pragma unroll
        for (int j = 0; j < 16; j++) a += sWl2[i*16+j]*hid[j];
        g_hl[ofs+i] = a;
        float qv = sbq[i], kv = sbk[i], gv = sbg[i];
        #pragma unroll
        for (int j = 0; j < 4; j++) {
            qv += sWq[i*4+j]*h0[j];
            kv += sWk[i*4+j]*h0[j];
            gv += sWg[i*4+j]*h0[j];
        }
        g_q[ofs+i] = qv; g_k[ofs+i] = kv; g_gg[ofs+i] = gv;
    }
}

// ============================================================
// Kernel 3: sim_prior = relu(E E^T).  grid (NC), 128 threads.
// ============================================================
__global__ void __launch_bounds__(128) prior_kernel(const float* __restrict__ E) {
    int c = blockIdx.x;
    __shared__ float ec[16];
    if (threadIdx.x < 16) ec[threadIdx.x] = E[c*16 + threadIdx.x];
    __syncthreads();
    for (int d = threadIdx.x; d < NC; d += blockDim.x) {
        const float* ed = E + d*16;
        float s = 0.f;
        #pragma unroll
        for (int j = 0; j < 16; j++) s += ec[j]*ed[j];
        g_prior[(size_t)c*NC + d] = fmaxf(s, 0.f);
    }
}

// ============================================================
// Kernel 4: tiled rows. grid (NC/8, NB), 128 threads (4 warps),
// 8 rows per block, 2 rows per warp. K then G staged in one
// 32KB transposed smem buffer (conflict-free lane-consecutive d).
// ============================================================
__global__ void __launch_bounds__(128) row_kernel(
    const float* __restrict__ Wf, const float* __restrict__ bf,
    const float* __restrict__ Wo, const float* __restrict__ bo,
    const float* __restrict__ lng, const float* __restrict__ lnb,
    float* __restrict__ out_alpha, float* __restrict__ out_A)
{
    __shared__ float sT[16][512];          // 32 KB, K then G (transposed)
    __shared__ float sQ[8][16];
    __shared__ float sHL[8][16];
    __shared__ float sGG[8][16];
    __shared__ float sWf[16][17];          // padded: conflict-free per-lane rows
    __shared__ float sbf[16], sWo[16], slng[16], slnb[16];
    __shared__ float sbo;

    int b = blockIdx.y;
    int c0 = blockIdx.x * 8;
    int t = threadIdx.x;
    int lane = t & 31, warp = t >> 5;

    if (t < 16) { sbf[t]=bf[t]; sWo[t]=Wo[t]; slng[t]=lng[t]; slnb[t]=lnb[t]; }
    if (t == 16) sbo = bo[0];
    if (t >= 32 && t < 48) {
        int i = t - 32;
        #pragma unroll
        for (int j = 0; j < 16; j++) sWf[i][j] = Wf[i*16+j];
    }
    {   // per-row vectors: 8 rows x 16
        int r = t >> 4, j = t & 15;
        size_t o = ((size_t)b*NC + c0 + r)*NH + j;
        sQ[r][j] = g_q[o]; sHL[r][j] = g_hl[o]; sGG[r][j] = g_gg[o];
    }
    // stage K transposed
    for (int idx = t; idx < 2048; idx += 128) {
        int d = idx >> 2, p = idx & 3;
        float4 v = __ldg(((const float4*)(g_k + ((size_t)b*NC + d)*NH)) + p);
        sT[p*4+0][d]=v.x; sT[p*4+1][d]=v.y; sT[p*4+2][d]=v.z; sT[p*4+3][d]=v.w;
    }
    __syncthreads();

    float av[2][16];                       // softmax weights, both rows
    #pragma unroll
    for (int rr = 0; rr < 2; rr++) {
        int r = warp*2 + rr;
        int c = c0 + r;
        float q[16];
        #pragma unroll
        for (int j = 0; j < 16; j++) q[j] = sQ[r][j];
        float sv[16];
        #pragma unroll
        for (int i = 0; i < 16; i++) {
            int d = lane + 32*i;
            float dot = 0.f;
            #pragma unroll
            for (int j = 0; j < 16; j++) dot += q[j]*sT[j][d];
            float s = fmaxf(dot, 0.f) + 0.2f*__ldg(g_prior + (size_t)c*NC + d);
            if (d == c) s += 1.f;
            sv[i] = s;
        }
        float mx = sv[0];
        #pragma unroll
        for (int i = 1; i < 16; i++) mx = fmaxf(mx, sv[i]);
        #pragma unroll
        for (int off = 16; off; off >>= 1)
            mx = fmaxf(mx, __shfl_xor_sync(0xffffffffu, mx, off));
        float sum = 0.f;
        #pragma unroll
        for (int i = 0; i < 16; i++) { sv[i] = __expf(sv[i]-mx); sum += sv[i]; }
        #pragma unroll
        for (int off = 16; off; off >>= 1)
            sum += __shfl_xor_sync(0xffffffffu, sum, off);
        float inv = __frcp_rn(sum);
        float* Arow = out_A + ((size_t)b*NC + c)*NC;
        #pragma unroll
        for (int i = 0; i < 16; i++) {
            float a = sv[i]*inv;
            av[rr][i] = a;
            Arow[lane + 32*i] = a;
        }
    }
    __syncthreads();
    // stage G transposed (reuse buffer)
    for (int idx = t; idx < 2048; idx += 128) {
        int d = idx >> 2, p = idx & 3;
        float4 v = __ldg(((const float4*)(g_gg + ((size_t)b*NC + d)*NH)) + p);
        sT[p*4+0][d]=v.x; sT[p*4+1][d]=v.y; sT[p*4+2][d]=v.z; sT[p*4+3][d]=v.w;
    }
    __syncthreads();

    #pragma unroll
    for (int rr = 0; rr < 2; rr++) {
        int r = warp*2 + rr;
        int c = c0 + r;
        float acc[16];
        #pragma unroll
        for (int h = 0; h < 16; h++) acc[h] = 0.f;
        #pragma unroll
        for (int i = 0; i < 16; i++) {
            int d = lane + 32*i;
            float a = av[rr][i];
            #pragma unroll
            for (int h = 0; h < 16; h++) acc[h] += a*sT[h][d];
        }
        #pragma unroll
        for (int off = 16; off; off >>= 1) {
            #pragma unroll
            for (int h = 0; h < 16; h++)
                acc[h] += __shfl_xor_sync(0xffffffffu, acc[h], off);
        }
        // epilogue (h, LN redundant on all lanes; Wf lane-parallel)
        float hv[16], musum = 0.f;
        #pragma unroll
        for (int j = 0; j < 16; j++) {
            float hg = sGG[r][j] + 0.3f*fmaxf(acc[j], 0.f);
            hv[j] = sHL[r][j] + 0.1f*hg;
            musum += hv[j];
        }
        float mu = musum*(1.f/16.f);
        float var = 0.f;
        #pragma unroll
        for (int j = 0; j < 16; j++) { float dd = hv[j]-mu; var += dd*dd; }
        var *= (1.f/16.f);
        float rinv = rsqrtf(var + 1e-5f);
        float v = 0.f;
        if (lane < 16) {
            float a2 = sbf[lane];
            #pragma unroll
            for (int j = 0; j < 16; j++) {
                float hn = (hv[j]-mu)*rinv*slng[j] + slnb[j];
                a2 += sWf[lane][j]*hn;
            }
            v = sWo[lane]*fmaxf(a2, 0.f);
        }
        #pragma unroll
        for (int off = 16; off; off >>= 1)
            v += __shfl_xor_sync(0xffffffffu, v, off);
        if (lane == 0)
            out_alpha[(size_t)b*NC + c] = 1.2f + 0.3f*tanhf(v + sbo);
    }
}

// ============================================================
extern "C" void kernel_launch(void* const* d_in, const int* in_sizes, int n_in,
                              void* d_out, int out_size)
{
    const float* res = (const float*)d_in[0];
    const float* emb = (const float*)d_in[1];
    const float* Wl1 = (const float*)d_in[2];
    const float* bl1 = (const float*)d_in[3];
    const float* Wl2 = (const float*)d_in[4];
    const float* bl2 = (const float*)d_in[5];
    const float* Wg  = (const float*)d_in[6];
    const float* bg  = (const float*)d_in[7];
    const float* Wq  = (const float*)d_in[8];
    const float* bq  = (const float*)d_in[9];
    const float* Wk  = (const float*)d_in[10];
    const float* bk  = (const float*)d_in[11];
    const float* Wf  = (const float*)d_in[12];
    const float* bf  = (const float*)d_in[13];
    const float* Wo  = (const float*)d_in[14];
    const float* bo  = (const float*)d_in[15];
    const float* lng = (const float*)d_in[16];
    const float* lnb = (const float*)d_in[17];

    float* out       = (float*)d_out;
    float* out_alpha = out;                       // [B,1,C]
    float* out_h0    = out + NB*NC;               // [B,C,4]
    float* out_A     = out + NB*NC + NB*NC*4;     // [B,C,C]

    stats_partial<<<dim3(NS, NB), 128>>>(res);
    prior_kernel <<<NC, 128>>>(emb);
    stats_final  <<<dim3(4, NB), 128>>>(Wl1,bl1,Wl2,bl2,Wg,bg,Wq,bq,Wk,bk,out_h0);
    row_kernel   <<<dim3(NC/8, NB), 128>>>(Wf,bf,Wo,bo,lng,lnb,out_alpha,out_A);
}

// round 8
// speedup vs baseline: 1.5047x; 1.1226x over previous
#include <cuda_runtime.h>
#include <math.h>

#define NB 8
#define NL 8192
#define NC 512
#define NH 16
#define NS 128          // L-slices for stats partial reduction
#define LS (NL/NS)      // 64 rows per slice

// ---- scratch (no allocations allowed) ----
__device__ float g_part[NB*NS*3*NC];   // [b][s][comp:{sumabs,max,sumsq}][c]  (6 MB)
__device__ float g_q [NB*NC*NH];
__device__ float g_k [NB*NC*NH];
__device__ float g_gg[NB*NC*NH];       // h_graph_in
__device__ float g_hl[NB*NC*NH];       // h_local
__device__ float g_prior[NC*NC];       // relu(E E^T)  (1 MB)

// ============================================================
// Kernel 1: streaming stats over L.  grid (NS, NB), 128 threads.
// ============================================================
__global__ void __launch_bounds__(128) stats_partial(const float* __restrict__ r) {
    int s = blockIdx.x, b = blockIdx.y;
    int t = threadIdx.x;
    const float* base = r + ((size_t)b*NL + (size_t)s*LS)*NC + t*4;
    float4 s1 = make_float4(0.f,0.f,0.f,0.f);
    float4 s2 = make_float4(0.f,0.f,0.f,0.f);
    float4 mx = make_float4(0.f,0.f,0.f,0.f);
    #pragma unroll 8
    for (int l = 0; l < LS; l++) {
        float4 v = __ldg((const float4*)(base + (size_t)l*NC));
        float ax = fabsf(v.x), ay = fabsf(v.y), az = fabsf(v.z), aw = fabsf(v.w);
        s1.x += ax; s1.y += ay; s1.z += az; s1.w += aw;
        s2.x += v.x*v.x; s2.y += v.y*v.y; s2.z += v.z*v.z; s2.w += v.w*v.w;
        mx.x = fmaxf(mx.x, ax); mx.y = fmaxf(mx.y, ay);
        mx.z = fmaxf(mx.z, az); mx.w = fmaxf(mx.w, aw);
    }
    size_t o = (size_t)((b*NS + s)*3)*NC + t*4;
    *(float4*)(g_part + o         ) = s1;
    *(float4*)(g_part + o +   NC  ) = mx;
    *(float4*)(g_part + o + 2*NC  ) = s2;
}

// ============================================================
// Kernel 2: combine partials, compute h0 + small per-(b,c) MLPs.
// ============================================================
__global__ void __launch_bounds__(128) stats_final(
    const float* __restrict__ Wl1, const float* __restrict__ bl1,
    const float* __restrict__ Wl2, const float* __restrict__ bl2,
    const float* __restrict__ Wg,  const float* __restrict__ bg,
    const float* __restrict__ Wq,  const float* __restrict__ bq,
    const float* __restrict__ Wk,  const float* __restrict__ bk,
    float* __restrict__ h0_out)
{
    int b = blockIdx.y;
    int c = blockIdx.x*128 + threadIdx.x;
    int t = threadIdx.x;

    __shared__ float sWl1[64], sWl2[256], sWg[64], sWq[64], sWk[64];
    __shared__ float sbl1[16], sbl2[16], sbg[16], sbq[16], sbk[16];
    if (t < 64) { sWl1[t]=Wl1[t]; sWg[t]=Wg[t]; sWq[t]=Wq[t]; sWk[t]=Wk[t]; }
    if (t >= 64 && t < 80) {
        int i = t-64;
        sbl1[i]=bl1[i]; sbl2[i]=bl2[i]; sbg[i]=bg[i]; sbq[i]=bq[i]; sbk[i]=bk[i];
    }
    sWl2[t] = Wl2[t]; sWl2[t+128] = Wl2[t+128];
    __syncthreads();

    float s1 = 0.f, s2 = 0.f, mx = 0.f;
    for (int s = 0; s < NS; s++) {
        size_t o = (size_t)((b*NS + s)*3)*NC + c;
        s1 += g_part[o];
        mx  = fmaxf(mx, g_part[o + NC]);
        s2 += g_part[o + 2*NC];
    }
    float m  = s1 * (1.f/NL);
    float sq = s2 * (1.f/NL);
    float sd = sqrtf(fmaxf(sq - m*m, 0.f));
    float h0[4] = { m, mx, sd, sq };
    *(float4*)(h0_out + ((size_t)b*NC + c)*4) = make_float4(m, mx, sd, sq);

    float hid[16];
    #pragma unroll
    for (int i = 0; i < 16; i++) {
        float a = sbl1[i];
        #pragma unroll
        for (int j = 0; j < 4; j++) a += sWl1[i*4+j]*h0[j];
        hid[i] = fmaxf(a, 0.f);
    }
    size_t ofs = ((size_t)b*NC + c)*NH;
    #pragma unroll
    for (int i = 0; i < 16; i++) {
        float a = sbl2[i];
        #pragma unroll
        for (int j = 0; j < 16; j++) a += sWl2[i*16+j]*hid[j];
        g_hl[ofs+i] = a;
        float qv = sbq[i], kv = sbk[i], gv = sbg[i];
        #pragma unroll
        for (int j = 0; j < 4; j++) {
            qv += sWq[i*4+j]*h0[j];
            kv += sWk[i*4+j]*h0[j];
            gv += sWg[i*4+j]*h0[j];
        }
        g_q[ofs+i] = qv; g_k[ofs+i] = kv; g_gg[ofs+i] = gv;
    }
}

// ============================================================
// Kernel 3: sim_prior = relu(E E^T).  grid (NC), 128 threads.
// ============================================================
__global__ void __launch_bounds__(128) prior_kernel(const float* __restrict__ E) {
    int c = blockIdx.x;
    __shared__ float ec[16];
    if (threadIdx.x < 16) ec[threadIdx.x] = E[c*16 + threadIdx.x];
    __syncthreads();
    for (int d = threadIdx.x; d < NC; d += blockDim.x) {
        const float* ed = E + d*16;
        float s = 0.f;
        #pragma unroll
        for (int j = 0; j < 16; j++) s += ec[j]*ed[j];
        g_prior[(size_t)c*NC + d] = fmaxf(s, 0.f);
    }
}

// ============================================================
// Kernel 4: tiled rows. grid (NC/4, NB), 128 threads (4 warps),
// ONE row per warp. Softmax weights parked in smem (sA) so no
// large register state lives across the K->G restage barrier.
// ============================================================
__global__ void __launch_bounds__(128) row_kernel(
    const float* __restrict__ Wf, const float* __restrict__ bf,
    const float* __restrict__ Wo, const float* __restrict__ bo,
    const float* __restrict__ lng, const float* __restrict__ lnb,
    float* __restrict__ out_alpha, float* __restrict__ out_A)
{
    __shared__ float sT[16][512];          // 32 KB, K then G (transposed)
    __shared__ float sA[4][512];           // 8 KB, softmax weights per row
    __shared__ float sQ[4][16];
    __shared__ float sHL[4][16];
    __shared__ float sGG[4][16];
    __shared__ float sWf[16][17];
    __shared__ float sbf[16], sWo[16], slng[16], slnb[16];
    __shared__ float sbo;

    int b = blockIdx.y;
    int c0 = blockIdx.x * 4;
    int t = threadIdx.x;
    int lane = t & 31, warp = t >> 5;

    if (t < 16) { sbf[t]=bf[t]; sWo[t]=Wo[t]; slng[t]=lng[t]; slnb[t]=lnb[t]; }
    if (t == 16) sbo = bo[0];
    if (t >= 32 && t < 48) {
        int i = t - 32;
        #pragma unroll
        for (int j = 0; j < 16; j++) sWf[i][j] = Wf[i*16+j];
    }
    if (t < 64) {                          // 4 rows x 16
        int r = t >> 4, j = t & 15;
        size_t o = ((size_t)b*NC + c0 + r)*NH + j;
        sQ[r][j] = g_q[o]; sHL[r][j] = g_hl[o]; sGG[r][j] = g_gg[o];
    }
    // stage K transposed
    #pragma unroll
    for (int ii = 0; ii < 16; ii++) {
        int idx = t + ii*128;
        int d = idx >> 2, p = idx & 3;
        float4 v = __ldg(((const float4*)(g_k + ((size_t)b*NC + d)*NH)) + p);
        sT[p*4+0][d]=v.x; sT[p*4+1][d]=v.y; sT[p*4+2][d]=v.z; sT[p*4+3][d]=v.w;
    }
    __syncthreads();

    {   // ---- phase 1: sim + softmax for this warp's row ----
        int r = warp, c = c0 + r;
        float q[16];
        #pragma unroll
        for (int j = 0; j < 16; j++) q[j] = sQ[r][j];
        float sv[16];
        #pragma unroll
        for (int i = 0; i < 16; i++) {
            int d = lane + 32*i;
            float dot = 0.f;
            #pragma unroll
            for (int j = 0; j < 16; j++) dot += q[j]*sT[j][d];
            float s = fmaxf(dot, 0.f) + 0.2f*__ldg(g_prior + (size_t)c*NC + d);
            if (d == c) s += 1.f;
            sv[i] = s;
        }
        float mx = sv[0];
        #pragma unroll
        for (int i = 1; i < 16; i++) mx = fmaxf(mx, sv[i]);
        #pragma unroll
        for (int off = 16; off; off >>= 1)
            mx = fmaxf(mx, __shfl_xor_sync(0xffffffffu, mx, off));
        float sum = 0.f;
        #pragma unroll
        for (int i = 0; i < 16; i++) { sv[i] = __expf(sv[i]-mx); sum += sv[i]; }
        #pragma unroll
        for (int off = 16; off; off >>= 1)
            sum += __shfl_xor_sync(0xffffffffu, sum, off);
        float inv = __frcp_rn(sum);
        float* Arow = out_A + ((size_t)b*NC + c)*NC;
        #pragma unroll
        for (int i = 0; i < 16; i++) {
            float a = sv[i]*inv;
            int d = lane + 32*i;
            Arow[d] = a;
            sA[r][d] = a;
        }
    }
    __syncthreads();
    // stage G transposed (reuse buffer)
    #pragma unroll
    for (int ii = 0; ii < 16; ii++) {
        int idx = t + ii*128;
        int d = idx >> 2, p = idx & 3;
        float4 v = __ldg(((const float4*)(g_gg + ((size_t)b*NC + d)*NH)) + p);
        sT[p*4+0][d]=v.x; sT[p*4+1][d]=v.y; sT[p*4+2][d]=v.z; sT[p*4+3][d]=v.w;
    }
    __syncthreads();

    {   // ---- phase 2: msg GEMV + epilogue ----
        int r = warp, c = c0 + r;
        float acc[16];
        #pragma unroll
        for (int h = 0; h < 16; h++) acc[h] = 0.f;
        #pragma unroll
        for (int i = 0; i < 16; i++) {
            int d = lane + 32*i;
            float a = sA[r][d];
            #pragma unroll
            for (int h = 0; h < 16; h++) acc[h] += a*sT[h][d];
        }
        #pragma unroll
        for (int off = 16; off; off >>= 1) {
            #pragma unroll
            for (int h = 0; h < 16; h++)
                acc[h] += __shfl_xor_sync(0xffffffffu, acc[h], off);
        }
        float hv[16], musum = 0.f;
        #pragma unroll
        for (int j = 0; j < 16; j++) {
            float hg = sGG[r][j] + 0.3f*fmaxf(acc[j], 0.f);
            hv[j] = sHL[r][j] + 0.1f*hg;
            musum += hv[j];
        }
        float mu = musum*(1.f/16.f);
        float var = 0.f;
        #pragma unroll
        for (int j = 0; j < 16; j++) { float dd = hv[j]-mu; var += dd*dd; }
        var *= (1.f/16.f);
        float rinv = rsqrtf(var + 1e-5f);
        float v = 0.f;
        if (lane < 16) {
            float a2 = sbf[lane];
            #pragma unroll
            for (int j = 0; j < 16; j++) {
                float hn = (hv[j]-mu)*rinv*slng[j] + slnb[j];
                a2 += sWf[lane][j]*hn;
            }
            v = sWo[lane]*fmaxf(a2, 0.f);
        }
        #pragma unroll
        for (int off = 16; off; off >>= 1)
            v += __shfl_xor_sync(0xffffffffu, v, off);
        if (lane == 0)
            out_alpha[(size_t)b*NC + c] = 1.2f + 0.3f*tanhf(v + sbo);
    }
}

// ============================================================
extern "C" void kernel_launch(void* const* d_in, const int* in_sizes, int n_in,
                              void* d_out, int out_size)
{
    const float* res = (const float*)d_in[0];
    const float* emb = (const float*)d_in[1];
    const float* Wl1 = (const float*)d_in[2];
    const float* bl1 = (const float*)d_in[3];
    const float* Wl2 = (const float*)d_in[4];
    const float* bl2 = (const float*)d_in[5];
    const float* Wg  = (const float*)d_in[6];
    const float* bg  = (const float*)d_in[7];
    const float* Wq  = (const float*)d_in[8];
    const float* bq  = (const float*)d_in[9];
    const float* Wk  = (const float*)d_in[10];
    const float* bk  = (const float*)d_in[11];
    const float* Wf  = (const float*)d_in[12];
    const float* bf  = (const float*)d_in[13];
    const float* Wo  = (const float*)d_in[14];
    const float* bo  = (const float*)d_in[15];
    const float* lng = (const float*)d_in[16];
    const float* lnb = (const float*)d_in[17];

    float* out       = (float*)d_out;
    float* out_alpha = out;                       // [B,1,C]
    float* out_h0    = out + NB*NC;               // [B,C,4]
    float* out_A     = out + NB*NC + NB*NC*4;     // [B,C,C]

    stats_partial<<<dim3(NS, NB), 128>>>(res);
    prior_kernel <<<NC, 128>>>(emb);
    stats_final  <<<dim3(4, NB), 128>>>(Wl1,bl1,Wl2,bl2,Wg,bg,Wq,bq,Wk,bk,out_h0);
    row_kernel   <<<dim3(NC/4, NB), 128>>>(Wf,bf,Wo,bo,lng,lnb,out_alpha,out_A);
}

// round 11
// speedup vs baseline: 1.5294x; 1.0164x over previous
#include <cuda_runtime.h>
#include <math.h>

#define NB 8
#define NL 8192
#define NC 512
#define NH 16
#define NS 128          // L-slices for stats partial reduction
#define LS (NL/NS)      // 64 rows per slice

// ---- scratch (no allocations allowed) ----
__device__ float g_part[NB*NS*3*NC];   // [b][s][comp:{sumabs,max,sumsq}][c]  (6 MB)
__device__ float g_q [NB*NC*NH];
__device__ float g_k [NB*NC*NH];
__device__ float g_gg[NB*NC*NH];       // h_graph_in
__device__ float g_hl[NB*NC*NH];       // h_local
__device__ float g_prior[NC*NC];       // relu(E E^T)  (1 MB)

// ============================================================
// Kernel 1: streaming stats over L.  grid (NS, NB), 128 threads.
// ============================================================
__global__ void __launch_bounds__(128) stats_partial(const float* __restrict__ r) {
    int s = blockIdx.x, b = blockIdx.y;
    int t = threadIdx.x;
    const float* base = r + ((size_t)b*NL + (size_t)s*LS)*NC + t*4;
    float4 s1 = make_float4(0.f,0.f,0.f,0.f);
    float4 s2 = make_float4(0.f,0.f,0.f,0.f);
    float4 mx = make_float4(0.f,0.f,0.f,0.f);
    #pragma unroll 8
    for (int l = 0; l < LS; l++) {
        float4 v = __ldg((const float4*)(base + (size_t)l*NC));
        float ax = fabsf(v.x), ay = fabsf(v.y), az = fabsf(v.z), aw = fabsf(v.w);
        s1.x += ax; s1.y += ay; s1.z += az; s1.w += aw;
        s2.x += v.x*v.x; s2.y += v.y*v.y; s2.z += v.z*v.z; s2.w += v.w*v.w;
        mx.x = fmaxf(mx.x, ax); mx.y = fmaxf(mx.y, ay);
        mx.z = fmaxf(mx.z, az); mx.w = fmaxf(mx.w, aw);
    }
    size_t o = (size_t)((b*NS + s)*3)*NC + t*4;
    *(float4*)(g_part + o         ) = s1;
    *(float4*)(g_part + o +   NC  ) = mx;
    *(float4*)(g_part + o + 2*NC  ) = s2;
}

// ============================================================
// Kernel 2: combine partials (parallel s-reduction, 512 thr),
// compute h0 + small per-(b,c) MLPs.  grid (4, NB).
// ============================================================
__global__ void __launch_bounds__(512) stats_final(
    const float* __restrict__ Wl1, const float* __restrict__ bl1,
    const float* __restrict__ Wl2, const float* __restrict__ bl2,
    const float* __restrict__ Wg,  const float* __restrict__ bg,
    const float* __restrict__ Wq,  const float* __restrict__ bq,
    const float* __restrict__ Wk,  const float* __restrict__ bk,
    float* __restrict__ h0_out)
{
    int b = blockIdx.y;
    int t = threadIdx.x;
    int cl = t & 127;               // c within 128-chunk
    int sg = t >> 7;                // s-group 0..3

    __shared__ float red[3][4][128];
    __shared__ float sWl1[64], sWl2[256], sWg[64], sWq[64], sWk[64];
    __shared__ float sbl1[16], sbl2[16], sbg[16], sbq[16], sbk[16];
    if (t < 64) { sWl1[t]=Wl1[t]; sWg[t]=Wg[t]; sWq[t]=Wq[t]; sWk[t]=Wk[t]; }
    if (t >= 64 && t < 80) {
        int i = t-64;
        sbl1[i]=bl1[i]; sbl2[i]=bl2[i]; sbg[i]=bg[i]; sbq[i]=bq[i]; sbk[i]=bk[i];
    }
    if (t >= 128 && t < 384) sWl2[t-128] = Wl2[t-128];

    int c = blockIdx.x*128 + cl;
    float s1 = 0.f, s2 = 0.f, mx = 0.f;
    #pragma unroll 4
    for (int s = sg*32; s < sg*32 + 32; s++) {
        size_t o = (size_t)((b*NS + s)*3)*NC + c;
        s1 += g_part[o];
        mx  = fmaxf(mx, g_part[o + NC]);
        s2 += g_part[o + 2*NC];
    }
    red[0][sg][cl] = s1; red[1][sg][cl] = mx; red[2][sg][cl] = s2;
    __syncthreads();

    if (t < 128) {
        s1 = (red[0][0][cl] + red[0][1][cl]) + (red[0][2][cl] + red[0][3][cl]);
        mx = fmaxf(fmaxf(red[1][0][cl], red[1][1][cl]),
                   fmaxf(red[1][2][cl], red[1][3][cl]));
        s2 = (red[2][0][cl] + red[2][1][cl]) + (red[2][2][cl] + red[2][3][cl]);

        float m  = s1 * (1.f/NL);
        float sq = s2 * (1.f/NL);
        float sd = sqrtf(fmaxf(sq - m*m, 0.f));
        float h0[4] = { m, mx, sd, sq };
        *(float4*)(h0_out + ((size_t)b*NC + c)*4) = make_float4(m, mx, sd, sq);

        float hid[16];
        #pragma unroll
        for (int i = 0; i < 16; i++) {
            float a = sbl1[i];
            #pragma unroll
            for (int j = 0; j < 4; j++) a += sWl1[i*4+j]*h0[j];
            hid[i] = fmaxf(a, 0.f);
        }
        size_t ofs = ((size_t)b*NC + c)*NH;
        #pragma unroll
        for (int i = 0; i < 16; i++) {
            float a = sbl2[i];
            #pragma unroll
            for (int j = 0; j < 16; j++) a += sWl2[i*16+j]*hid[j];
            g_hl[ofs+i] = a;
            float qv = sbq[i], kv = sbk[i], gv = sbg[i];
            #pragma unroll
            for (int j = 0; j < 4; j++) {
                qv += sWq[i*4+j]*h0[j];
                kv += sWk[i*4+j]*h0[j];
                gv += sWg[i*4+j]*h0[j];
            }
            g_q[ofs+i] = qv; g_k[ofs+i] = kv; g_gg[ofs+i] = gv;
        }
    }
}

// ============================================================
// Kernel 3: sim_prior = relu(E E^T).  grid (NC), 128 threads.
// ============================================================
__global__ void __launch_bounds__(128) prior_kernel(const float* __restrict__ E) {
    int c = blockIdx.x;
    __shared__ float ec[16];
    if (threadIdx.x < 16) ec[threadIdx.x] = E[c*16 + threadIdx.x];
    __syncthreads();
    for (int d = threadIdx.x; d < NC; d += blockDim.x) {
        const float* ed = E + d*16;
        float s = 0.f;
        #pragma unroll
        for (int j = 0; j < 16; j++) s += ec[j]*ed[j];
        g_prior[(size_t)c*NC + d] = fmaxf(s, 0.f);
    }
}

// ============================================================
// Kernel 4: tiled rows. grid (NC/4, NB), 128 threads (4 warps),
// ONE row per warp. K/G staged as float4 (LDS.128, 4x fewer
// smem instructions than scalar). Softmax weights parked in sA.
// ============================================================
__global__ void __launch_bounds__(128) row_kernel(
    const float* __restrict__ Wf, const float* __restrict__ bf,
    const float* __restrict__ Wo, const float* __restrict__ bo,
    const float* __restrict__ lng, const float* __restrict__ lnb,
    float* __restrict__ out_alpha, float* __restrict__ out_A)
{
    __shared__ float4 sT4[4][512];         // 32 KB, K then G (packed float4)
    __shared__ float sA[4][512];           // 8 KB, softmax weights per row
    __shared__ float sQ[4][16];
    __shared__ float sHL[4][16];
    __shared__ float sGG[4][16];
    __shared__ float sWf[16][17];
    __shared__ float sbf[16], sWo[16], slng[16], slnb[16];
    __shared__ float sbo;

    int b = blockIdx.y;
    int c0 = blockIdx.x * 4;
    int t = threadIdx.x;
    int lane = t & 31, warp = t >> 5;

    if (t < 16) { sbf[t]=bf[t]; sWo[t]=Wo[t]; slng[t]=lng[t]; slnb[t]=lnb[t]; }
    if (t == 16) sbo = bo[0];
    if (t >= 32 && t < 48) {
        int i = t - 32;
        #pragma unroll
        for (int j = 0; j < 16; j++) sWf[i][j] = Wf[i*16+j];
    }
    if (t < 64) {                          // 4 rows x 16
        int r = t >> 4, j = t & 15;
        size_t o = ((size_t)b*NC + c0 + r)*NH + j;
        sQ[r][j] = g_q[o]; sHL[r][j] = g_hl[o]; sGG[r][j] = g_gg[o];
    }
    // stage K (float4 direct, conflict-free stores)
    #pragma unroll
    for (int ii = 0; ii < 16; ii++) {
        int idx = t + ii*128;
        int p = idx >> 9, d = idx & 511;
        sT4[p][d] = __ldg(((const float4*)(g_k + ((size_t)b*NC + d)*NH)) + p);
    }
    __syncthreads();

    {   // ---- phase 1: sim + softmax for this warp's row ----
        int r = warp, c = c0 + r;
        float q[16];
        #pragma unroll
        for (int j = 0; j < 16; j++) q[j] = sQ[r][j];
        float sv[16];
        #pragma unroll
        for (int i = 0; i < 16; i++) {
            int d = lane + 32*i;
            float4 k0 = sT4[0][d], k1 = sT4[1][d], k2 = sT4[2][d], k3 = sT4[3][d];
            float dot = q[0]*k0.x + q[1]*k0.y + q[2]*k0.z + q[3]*k0.w
                      + q[4]*k1.x + q[5]*k1.y + q[6]*k1.z + q[7]*k1.w
                      + q[8]*k2.x + q[9]*k2.y + q[10]*k2.z + q[11]*k2.w
                      + q[12]*k3.x + q[13]*k3.y + q[14]*k3.z + q[15]*k3.w;
            float s = fmaxf(dot, 0.f) + 0.2f*__ldg(g_prior + (size_t)c*NC + d);
            if (d == c) s += 1.f;
            sv[i] = s;
        }
        float mx = sv[0];
        #pragma unroll
        for (int i = 1; i < 16; i++) mx = fmaxf(mx, sv[i]);
        #pragma unroll
        for (int off = 16; off; off >>= 1)
            mx = fmaxf(mx, __shfl_xor_sync(0xffffffffu, mx, off));
        float sum = 0.f;
        #pragma unroll
        for (int i = 0; i < 16; i++) { sv[i] = __expf(sv[i]-mx); sum += sv[i]; }
        #pragma unroll
        for (int off = 16; off; off >>= 1)
            sum += __shfl_xor_sync(0xffffffffu, sum, off);
        float inv = __frcp_rn(sum);
        float* Arow = out_A + ((size_t)b*NC + c)*NC;
        #pragma unroll
        for (int i = 0; i < 16; i++) {
            float a = sv[i]*inv;
            int d = lane + 32*i;
            Arow[d] = a;
            sA[r][d] = a;
        }
    }
    __syncthreads();
    // stage G (reuse buffer)
    #pragma unroll
    for (int ii = 0; ii < 16; ii++) {
        int idx = t + ii*128;
        int p = idx >> 9, d = idx & 511;
        sT4[p][d] = __ldg(((const float4*)(g_gg + ((size_t)b*NC + d)*NH)) + p);
    }
    __syncthreads();

    {   // ---- phase 2: msg GEMV + epilogue ----
        int r = warp, c = c0 + r;
        float acc[16];
        #pragma unroll
        for (int h = 0; h < 16; h++) acc[h] = 0.f;
        #pragma unroll
        for (int i = 0; i < 16; i++) {
            int d = lane + 32*i;
            float a = sA[r][d];
            float4 g0 = sT4[0][d], g1 = sT4[1][d], g2 = sT4[2][d], g3 = sT4[3][d];
            acc[0]+=a*g0.x;  acc[1]+=a*g0.y;  acc[2]+=a*g0.z;  acc[3]+=a*g0.w;
            acc[4]+=a*g1.x;  acc[5]+=a*g1.y;  acc[6]+=a*g1.z;  acc[7]+=a*g1.w;
            acc[8]+=a*g2.x;  acc[9]+=a*g2.y;  acc[10]+=a*g2.z; acc[11]+=a*g2.w;
            acc[12]+=a*g3.x; acc[13]+=a*g3.y; acc[14]+=a*g3.z; acc[15]+=a*g3.w;
        }
        #pragma unroll
        for (int off = 16; off; off >>= 1) {
            #pragma unroll
            for (int h = 0; h < 16; h++)
                acc[h] += __shfl_xor_sync(0xffffffffu, acc[h], off);
        }
        float hv[16], musum = 0.f;
        #pragma unroll
        for (int j = 0; j < 16; j++) {
            float hg = sGG[r][j] + 0.3f*fmaxf(acc[j], 0.f);
            hv[j] = sHL[r][j] + 0.1f*hg;
            musum += hv[j];
        }
        float mu = musum*(1.f/16.f);
        float var = 0.f;
        #pragma unroll
        for (int j = 0; j < 16; j++) { float dd = hv[j]-mu; var += dd*dd; }
        var *= (1.f/16.f);
        float rinv = rsqrtf(var + 1e-5f);
        float v = 0.f;
        if (lane < 16) {
            float a2 = sbf[lane];
            #pragma unroll
            for (int j = 0; j < 16; j++) {
                float hn = (hv[j]-mu)*rinv*slng[j] + slnb[j];
                a2 += sWf[lane][j]*hn;
            }
            v = sWo[lane]*fmaxf(a2, 0.f);
        }
        #pragma unroll
        for (int off = 16; off; off >>= 1)
            v += __shfl_xor_sync(0xffffffffu, v, off);
        if (lane == 0)
            out_alpha[(size_t)b*NC + c] = 1.2f + 0.3f*tanhf(v + sbo);
    }
}

// ============================================================
extern "C" void kernel_launch(void* const* d_in, const int* in_sizes, int n_in,
                              void* d_out, int out_size)
{
    const float* res = (const float*)d_in[0];
    const float* emb = (const float*)d_in[1];
    const float* Wl1 = (const float*)d_in[2];
    const float* bl1 = (const float*)d_in[3];
    const float* Wl2 = (const float*)d_in[4];
    const float* bl2 = (const float*)d_in[5];
    const float* Wg  = (const float*)d_in[6];
    const float* bg  = (const float*)d_in[7];
    const float* Wq  = (const float*)d_in[8];
    const float* bq  = (const float*)d_in[9];
    const float* Wk  = (const float*)d_in[10];
    const float* bk  = (const float*)d_in[11];
    const float* Wf  = (const float*)d_in[12];
    const float* bf  = (const float*)d_in[13];
    const float* Wo  = (const float*)d_in[14];
    const float* bo  = (const float*)d_in[15];
    const float* lng = (const float*)d_in[16];
    const float* lnb = (const float*)d_in[17];

    float* out       = (float*)d_out;
    float* out_alpha = out;                       // [B,1,C]
    float* out_h0    = out + NB*NC;               // [B,C,4]
    float* out_A     = out + NB*NC + NB*NC*4;     // [B,C,C]

    stats_partial<<<dim3(NS, NB), 128>>>(res);
    prior_kernel <<<NC, 128>>>(emb);
    stats_final  <<<dim3(4, NB), 512>>>(Wl1,bl1,Wl2,bl2,Wg,bg,Wq,bq,Wk,bk,out_h0);
    row_kernel   <<<dim3(NC/4, NB), 128>>>(Wf,bf,Wo,bo,lng,lnb,out_alpha,out_A);
}

// round 14
// speedup vs baseline: 1.6131x; 1.0547x over previous
#include <cuda_runtime.h>
#include <math.h>

#define NB 8
#define NL 8192
#define NC 512
#define NH 16
#define NS 128          // L-slices for stats partial reduction
#define LS (NL/NS)      // 64 rows per slice

// ---- scratch (no allocations allowed) ----
__device__ float g_part[NB*NS*3*NC];   // [b][s][comp:{sumabs,max,sumsq}][c]  (6 MB)
__device__ float g_q [NB*NC*NH];
__device__ float g_k [NB*NC*NH];
__device__ float g_gg[NB*NC*NH];       // h_graph_in
__device__ float g_hl[NB*NC*NH];       // h_local
__device__ float g_prior[NC*NC];       // relu(E E^T)  (1 MB)

// ============================================================
// Kernel 1: streaming stats over L.  grid (NS, NB), 128 threads.
// ============================================================
__global__ void __launch_bounds__(128) stats_partial(const float* __restrict__ r) {
    int s = blockIdx.x, b = blockIdx.y;
    int t = threadIdx.x;
    const float* base = r + ((size_t)b*NL + (size_t)s*LS)*NC + t*4;
    float4 s1 = make_float4(0.f,0.f,0.f,0.f);
    float4 s2 = make_float4(0.f,0.f,0.f,0.f);
    float4 mx = make_float4(0.f,0.f,0.f,0.f);
    #pragma unroll 8
    for (int l = 0; l < LS; l++) {
        float4 v = __ldg((const float4*)(base + (size_t)l*NC));
        float ax = fabsf(v.x), ay = fabsf(v.y), az = fabsf(v.z), aw = fabsf(v.w);
        s1.x += ax; s1.y += ay; s1.z += az; s1.w += aw;
        s2.x += v.x*v.x; s2.y += v.y*v.y; s2.z += v.z*v.z; s2.w += v.w*v.w;
        mx.x = fmaxf(mx.x, ax); mx.y = fmaxf(mx.y, ay);
        mx.z = fmaxf(mx.z, az); mx.w = fmaxf(mx.w, aw);
    }
    size_t o = (size_t)((b*NS + s)*3)*NC + t*4;
    *(float4*)(g_part + o         ) = s1;
    *(float4*)(g_part + o +   NC  ) = mx;
    *(float4*)(g_part + o + 2*NC  ) = s2;
}

// ============================================================
// Kernel 2: combine partials (parallel s-reduction, 512 thr),
// compute h0 + small per-(b,c) MLPs.  grid (4, NB).
// ============================================================
__global__ void __launch_bounds__(512) stats_final(
    const float* __restrict__ Wl1, const float* __restrict__ bl1,
    const float* __restrict__ Wl2, const float* __restrict__ bl2,
    const float* __restrict__ Wg,  const float* __restrict__ bg,
    const float* __restrict__ Wq,  const float* __restrict__ bq,
    const float* __restrict__ Wk,  const float* __restrict__ bk,
    float* __restrict__ h0_out)
{
    int b = blockIdx.y;
    int t = threadIdx.x;
    int cl = t & 127;               // c within 128-chunk
    int sg = t >> 7;                // s-group 0..3

    __shared__ float red[3][4][128];
    __shared__ float sWl1[64], sWl2[256], sWg[64], sWq[64], sWk[64];
    __shared__ float sbl1[16], sbl2[16], sbg[16], sbq[16], sbk[16];
    if (t < 64) { sWl1[t]=Wl1[t]; sWg[t]=Wg[t]; sWq[t]=Wq[t]; sWk[t]=Wk[t]; }
    if (t >= 64 && t < 80) {
        int i = t-64;
        sbl1[i]=bl1[i]; sbl2[i]=bl2[i]; sbg[i]=bg[i]; sbq[i]=bq[i]; sbk[i]=bk[i];
    }
    if (t >= 128 && t < 384) sWl2[t-128] = Wl2[t-128];

    int c = blockIdx.x*128 + cl;
    float s1 = 0.f, s2 = 0.f, mx = 0.f;
    #pragma unroll 4
    for (int s = sg*32; s < sg*32 + 32; s++) {
        size_t o = (size_t)((b*NS + s)*3)*NC + c;
        s1 += g_part[o];
        mx  = fmaxf(mx, g_part[o + NC]);
        s2 += g_part[o + 2*NC];
    }
    red[0][sg][cl] = s1; red[1][sg][cl] = mx; red[2][sg][cl] = s2;
    __syncthreads();

    if (t < 128) {
        s1 = (red[0][0][cl] + red[0][1][cl]) + (red[0][2][cl] + red[0][3][cl]);
        mx = fmaxf(fmaxf(red[1][0][cl], red[1][1][cl]),
                   fmaxf(red[1][2][cl], red[1][3][cl]));
        s2 = (red[2][0][cl] + red[2][1][cl]) + (red[2][2][cl] + red[2][3][cl]);

        float m  = s1 * (1.f/NL);
        float sq = s2 * (1.f/NL);
        float sd = sqrtf(fmaxf(sq - m*m, 0.f));
        float h0[4] = { m, mx, sd, sq };
        *(float4*)(h0_out + ((size_t)b*NC + c)*4) = make_float4(m, mx, sd, sq);

        float hid[16];
        #pragma unroll
        for (int i = 0; i < 16; i++) {
            float a = sbl1[i];
            #pragma unroll
            for (int j = 0; j < 4; j++) a += sWl1[i*4+j]*h0[j];
            hid[i] = fmaxf(a, 0.f);
        }
        size_t ofs = ((size_t)b*NC + c)*NH;
        #pragma unroll
        for (int i = 0; i < 16; i++) {
            float a = sbl2[i];
            #pragma unroll
            for (int j = 0; j < 16; j++) a += sWl2[i*16+j]*hid[j];
            g_hl[ofs+i] = a;
            float qv = sbq[i], kv = sbk[i], gv = sbg[i];
            #pragma unroll
            for (int j = 0; j < 4; j++) {
                qv += sWq[i*4+j]*h0[j];
                kv += sWk[i*4+j]*h0[j];
                gv += sWg[i*4+j]*h0[j];
            }
            g_q[ofs+i] = qv; g_k[ofs+i] = kv; g_gg[ofs+i] = gv;
        }
    }
}

// ============================================================
// Kernel 3: sim_prior = relu(E E^T).  grid (NC), 128 threads.
// ============================================================
__global__ void __launch_bounds__(128) prior_kernel(const float* __restrict__ E) {
    int c = blockIdx.x;
    __shared__ float ec[16];
    if (threadIdx.x < 16) ec[threadIdx.x] = E[c*16 + threadIdx.x];
    __syncthreads();
    for (int d = threadIdx.x; d < NC; d += blockDim.x) {
        const float* ed = E + d*16;
        float s = 0.f;
        #pragma unroll
        for (int j = 0; j < 16; j++) s += ec[j]*ed[j];
        g_prior[(size_t)c*NC + d] = fmaxf(s, 0.f);
    }
}

// ============================================================
// Kernel 4: tiled rows. grid (NC/8, NB), 256 threads (8 warps),
// ONE row per warp, 8 rows per block. Phase-2 softmax weights
// re-read from the just-written A row in gmem (thread-local
// coherence; L2-hot) so smem stays at ~33.5 KB -> ~6 blocks/SM.
// ============================================================
__global__ void __launch_bounds__(256) row_kernel(
    const float* __restrict__ Wf, const float* __restrict__ bf,
    const float* __restrict__ Wo, const float* __restrict__ bo,
    const float* __restrict__ lng, const float* __restrict__ lnb,
    float* __restrict__ out_alpha, float* __restrict__ out_A)
{
    __shared__ float4 sT4[4][512];         // 32 KB, K then G (packed float4)
    __shared__ float sQ[8][16];
    __shared__ float sHL[8][16];
    __shared__ float sGG[8][16];
    __shared__ float sWf[16][17];
    __shared__ float sbf[16], sWo[16], slng[16], slnb[16];
    __shared__ float sbo;

    int b = blockIdx.y;
    int c0 = blockIdx.x * 8;
    int t = threadIdx.x;
    int lane = t & 31, warp = t >> 5;

    if (t < 16) { sbf[t]=bf[t]; sWo[t]=Wo[t]; slng[t]=lng[t]; slnb[t]=lnb[t]; }
    if (t == 16) sbo = bo[0];
    if (t >= 32 && t < 48) {
        int i = t - 32;
        #pragma unroll
        for (int j = 0; j < 16; j++) sWf[i][j] = Wf[i*16+j];
    }
    if (t >= 128) {                        // 8 rows x 16
        int r = (t-128) >> 4, j = t & 15;
        size_t o = ((size_t)b*NC + c0 + r)*NH + j;
        sQ[r][j] = g_q[o]; sHL[r][j] = g_hl[o]; sGG[r][j] = g_gg[o];
    }
    // stage K (float4, 2048 loads over 256 threads)
    #pragma unroll
    for (int ii = 0; ii < 8; ii++) {
        int idx = t + ii*256;
        int p = idx >> 9, d = idx & 511;
        sT4[p][d] = __ldg(((const float4*)(g_k + ((size_t)b*NC + d)*NH)) + p);
    }
    __syncthreads();

    int r = warp, c = c0 + r;
    float* Arow = out_A + ((size_t)b*NC + c)*NC;

    {   // ---- phase 1: sim + softmax for this warp's row ----
        float q[16];
        #pragma unroll
        for (int j = 0; j < 16; j++) q[j] = sQ[r][j];
        float sv[16];
        #pragma unroll
        for (int i = 0; i < 16; i++) {
            int d = lane + 32*i;
            float4 k0 = sT4[0][d], k1 = sT4[1][d], k2 = sT4[2][d], k3 = sT4[3][d];
            float dot = q[0]*k0.x + q[1]*k0.y + q[2]*k0.z + q[3]*k0.w
                      + q[4]*k1.x + q[5]*k1.y + q[6]*k1.z + q[7]*k1.w
                      + q[8]*k2.x + q[9]*k2.y + q[10]*k2.z + q[11]*k2.w
                      + q[12]*k3.x + q[13]*k3.y + q[14]*k3.z + q[15]*k3.w;
            float s = fmaxf(dot, 0.f) + 0.2f*__ldg(g_prior + (size_t)c*NC + d);
            if (d == c) s += 1.f;
            sv[i] = s;
        }
        float mx = sv[0];
        #pragma unroll
        for (int i = 1; i < 16; i++) mx = fmaxf(mx, sv[i]);
        #pragma unroll
        for (int off = 16; off; off >>= 1)
            mx = fmaxf(mx, __shfl_xor_sync(0xffffffffu, mx, off));
        float sum = 0.f;
        #pragma unroll
        for (int i = 0; i < 16; i++) { sv[i] = __expf(sv[i]-mx); sum += sv[i]; }
        #pragma unroll
        for (int off = 16; off; off >>= 1)
            sum += __shfl_xor_sync(0xffffffffu, sum, off);
        float inv = __frcp_rn(sum);
        #pragma unroll
        for (int i = 0; i < 16; i++)
            Arow[lane + 32*i] = sv[i]*inv;
    }
    __syncthreads();
    // stage G (reuse buffer)
    #pragma unroll
    for (int ii = 0; ii < 8; ii++) {
        int idx = t + ii*256;
        int p = idx >> 9, d = idx & 511;
        sT4[p][d] = __ldg(((const float4*)(g_gg + ((size_t)b*NC + d)*NH)) + p);
    }
    __syncthreads();

    {   // ---- phase 2: msg GEMV + epilogue (A re-read from gmem) ----
        float acc[16];
        #pragma unroll
        for (int h = 0; h < 16; h++) acc[h] = 0.f;
        #pragma unroll
        for (int i = 0; i < 16; i++) {
            int d = lane + 32*i;
            float a = Arow[d];          // own prior write; plain load (not __ldg)
            float4 g0 = sT4[0][d], g1 = sT4[1][d], g2 = sT4[2][d], g3 = sT4[3][d];
            acc[0]+=a*g0.x;  acc[1]+=a*g0.y;  acc[2]+=a*g0.z;  acc[3]+=a*g0.w;
            acc[4]+=a*g1.x;  acc[5]+=a*g1.y;  acc[6]+=a*g1.z;  acc[7]+=a*g1.w;
            acc[8]+=a*g2.x;  acc[9]+=a*g2.y;  acc[10]+=a*g2.z; acc[11]+=a*g2.w;
            acc[12]+=a*g3.x; acc[13]+=a*g3.y; acc[14]+=a*g3.z; acc[15]+=a*g3.w;
        }
        #pragma unroll
        for (int off = 16; off; off >>= 1) {
            #pragma unroll
            for (int h = 0; h < 16; h++)
                acc[h] += __shfl_xor_sync(0xffffffffu, acc[h], off);
        }
        float hv[16], musum = 0.f;
        #pragma unroll
        for (int j = 0; j < 16; j++) {
            float hg = sGG[r][j] + 0.3f*fmaxf(acc[j], 0.f);
            hv[j] = sHL[r][j] + 0.1f*hg;
            musum += hv[j];
        }
        float mu = musum*(1.f/16.f);
        float var = 0.f;
        #pragma unroll
        for (int j = 0; j < 16; j++) { float dd = hv[j]-mu; var += dd*dd; }
        var *= (1.f/16.f);
        float rinv = rsqrtf(var + 1e-5f);
        float v = 0.f;
        if (lane < 16) {
            float a2 = sbf[lane];
            #pragma unroll
            for (int j = 0; j < 16; j++) {
                float hn = (hv[j]-mu)*rinv*slng[j] + slnb[j];
                a2 += sWf[lane][j]*hn;
            }
            v = sWo[lane]*fmaxf(a2, 0.f);
        }
        #pragma unroll
        for (int off = 16; off; off >>= 1)
            v += __shfl_xor_sync(0xffffffffu, v, off);
        if (lane == 0)
            out_alpha[(size_t)b*NC + c] = 1.2f + 0.3f*tanhf(v + sbo);
    }
}

// ============================================================
extern "C" void kernel_launch(void* const* d_in, const int* in_sizes, int n_in,
                              void* d_out, int out_size)
{
    const float* res = (const float*)d_in[0];
    const float* emb = (const float*)d_in[1];
    const float* Wl1 = (const float*)d_in[2];
    const float* bl1 = (const float*)d_in[3];
    const float* Wl2 = (const float*)d_in[4];
    const float* bl2 = (const float*)d_in[5];
    const float* Wg  = (const float*)d_in[6];
    const float* bg  = (const float*)d_in[7];
    const float* Wq  = (const float*)d_in[8];
    const float* bq  = (const float*)d_in[9];
    const float* Wk  = (const float*)d_in[10];
    const float* bk  = (const float*)d_in[11];
    const float* Wf  = (const float*)d_in[12];
    const float* bf  = (const float*)d_in[13];
    const float* Wo  = (const float*)d_in[14];
    const float* bo  = (const float*)d_in[15];
    const float* lng = (const float*)d_in[16];
    const float* lnb = (const float*)d_in[17];

    float* out       = (float*)d_out;
    float* out_alpha = out;                       // [B,1,C]
    float* out_h0    = out + NB*NC;               // [B,C,4]
    float* out_A     = out + NB*NC + NB*NC*4;     // [B,C,C]

    stats_partial<<<dim3(NS, NB), 128>>>(res);
    prior_kernel <<<NC, 128>>>(emb);
    stats_final  <<<dim3(4, NB), 512>>>(Wl1,bl1,Wl2,bl2,Wg,bg,Wq,bq,Wk,bk,out_h0);
    row_kernel   <<<dim3(NC/8, NB), 256>>>(Wf,bf,Wo,bo,lng,lnb,out_alpha,out_A);
}

// round 16
// speedup vs baseline: 1.7140x; 1.0625x over previous
#include <cuda_runtime.h>
#include <math.h>

#define NB 8
#define NL 8192
#define NC 512
#define NH 16
#define NS 128          // L-slices for stats partial reduction
#define LS (NL/NS)      // 64 rows per slice

// ---- scratch (no allocations allowed) ----
__device__ float g_part[NB*NS*3*NC];   // [b][s][comp][c]  (6 MB)
__device__ float g_q [NB*NC*NH];
__device__ float g_k [NB*NC*NH];
__device__ float g_gg[NB*NC*NH];       // h_graph_in
__device__ float g_hl[NB*NC*NH];       // h_local
__device__ float g_prior[NC*NC];       // relu(E E^T)  (1 MB)

// ============================================================
// Kernel 1: streaming stats over L.  grid (NS, NB), 128 threads.
// ============================================================
__global__ void __launch_bounds__(128) stats_partial(const float* __restrict__ r) {
    int s = blockIdx.x, b = blockIdx.y;
    int t = threadIdx.x;
    const float* base = r + ((size_t)b*NL + (size_t)s*LS)*NC + t*4;
    float4 s1 = make_float4(0.f,0.f,0.f,0.f);
    float4 s2 = make_float4(0.f,0.f,0.f,0.f);
    float4 mx = make_float4(0.f,0.f,0.f,0.f);
    #pragma unroll 8
    for (int l = 0; l < LS; l++) {
        float4 v = __ldg((const float4*)(base + (size_t)l*NC));
        float ax = fabsf(v.x), ay = fabsf(v.y), az = fabsf(v.z), aw = fabsf(v.w);
        s1.x += ax; s1.y += ay; s1.z += az; s1.w += aw;
        s2.x += v.x*v.x; s2.y += v.y*v.y; s2.z += v.z*v.z; s2.w += v.w*v.w;
        mx.x = fmaxf(mx.x, ax); mx.y = fmaxf(mx.y, ay);
        mx.z = fmaxf(mx.z, az); mx.w = fmaxf(mx.w, aw);
    }
    size_t o = (size_t)((b*NS + s)*3)*NC + t*4;
    *(float4*)(g_part + o         ) = s1;
    *(float4*)(g_part + o +   NC  ) = mx;
    *(float4*)(g_part + o + 2*NC  ) = s2;
}

// ============================================================
// Kernel 2: combine partials.  grid (16, NB), 128 threads.
// 32 c per block; 4 s-groups of 32; t<32 finishes + runs MLPs.
// ============================================================
__global__ void __launch_bounds__(128) stats_final(
    const float* __restrict__ Wl1, const float* __restrict__ bl1,
    const float* __restrict__ Wl2, const float* __restrict__ bl2,
    const float* __restrict__ Wg,  const float* __restrict__ bg,
    const float* __restrict__ Wq,  const float* __restrict__ bq,
    const float* __restrict__ Wk,  const float* __restrict__ bk,
    float* __restrict__ h0_out)
{
    int b = blockIdx.y;
    int t = threadIdx.x;
    int cl = t & 31;                // c within 32-chunk
    int sg = t >> 5;                // s-group 0..3

    __shared__ float red[3][4][32];
    __shared__ float sWl1[64], sWl2[256], sWg[64], sWq[64], sWk[64];
    __shared__ float sbl1[16], sbl2[16], sbg[16], sbq[16], sbk[16];
    if (t < 64) { sWl1[t]=Wl1[t]; sWg[t]=Wg[t]; sWq[t]=Wq[t]; sWk[t]=Wk[t]; }
    if (t >= 64 && t < 80) {
        int i = t-64;
        sbl1[i]=bl1[i]; sbl2[i]=bl2[i]; sbg[i]=bg[i]; sbq[i]=bq[i]; sbk[i]=bk[i];
    }
    sWl2[t] = Wl2[t]; sWl2[t+128] = Wl2[t+128];

    int c = blockIdx.x*32 + cl;
    float s1 = 0.f, s2 = 0.f, mx = 0.f;
    #pragma unroll 8
    for (int s = sg*32; s < sg*32 + 32; s++) {
        size_t o = (size_t)((b*NS + s)*3)*NC + c;
        s1 += g_part[o];
        mx  = fmaxf(mx, g_part[o + NC]);
        s2 += g_part[o + 2*NC];
    }
    red[0][sg][cl] = s1; red[1][sg][cl] = mx; red[2][sg][cl] = s2;
    __syncthreads();

    if (t < 32) {
        s1 = (red[0][0][cl] + red[0][1][cl]) + (red[0][2][cl] + red[0][3][cl]);
        mx = fmaxf(fmaxf(red[1][0][cl], red[1][1][cl]),
                   fmaxf(red[1][2][cl], red[1][3][cl]));
        s2 = (red[2][0][cl] + red[2][1][cl]) + (red[2][2][cl] + red[2][3][cl]);

        float m  = s1 * (1.f/NL);
        float sq = s2 * (1.f/NL);
        float sd = sqrtf(fmaxf(sq - m*m, 0.f));
        float h0[4] = { m, mx, sd, sq };
        *(float4*)(h0_out + ((size_t)b*NC + c)*4) = make_float4(m, mx, sd, sq);

        float hid[16];
        #pragma unroll
        for (int i = 0; i < 16; i++) {
            float a = sbl1[i];
            #pragma unroll
            for (int j = 0; j < 4; j++) a += sWl1[i*4+j]*h0[j];
            hid[i] = fmaxf(a, 0.f);
        }
        size_t ofs = ((size_t)b*NC + c)*NH;
        #pragma unroll
        for (int i = 0; i < 16; i++) {
            float a = sbl2[i];
            #pragma unroll
            for (int j = 0; j < 16; j++) a += sWl2[i*16+j]*hid[j];
            g_hl[ofs+i] = a;
            float qv = sbq[i], kv = sbk[i], gv = sbg[i];
            #pragma unroll
            for (int j = 0; j < 4; j++) {
                qv += sWq[i*4+j]*h0[j];
                kv += sWk[i*4+j]*h0[j];
                gv += sWg[i*4+j]*h0[j];
            }
            g_q[ofs+i] = qv; g_k[ofs+i] = kv; g_gg[ofs+i] = gv;
        }
    }
}

// ============================================================
// Kernel 3: sim_prior = relu(E E^T).  grid (NC), 128 threads.
// ============================================================
__global__ void __launch_bounds__(128) prior_kernel(const float* __restrict__ E) {
    int c = blockIdx.x;
    __shared__ float ec[16];
    if (threadIdx.x < 16) ec[threadIdx.x] = E[c*16 + threadIdx.x];
    __syncthreads();
    for (int d = threadIdx.x; d < NC; d += blockDim.x) {
        const float* ed = E + d*16;
        float s = 0.f;
        #pragma unroll
        for (int j = 0; j < 16; j++) s += ec[j]*ed[j];
        g_prior[(size_t)c*NC + d] = fmaxf(s, 0.f);
    }
}

// ============================================================
// Kernel 4: grid (NC/4, NB), 256 threads (8 warps), 4 rows per
// block, TWO warps per row (each handles 256 d's). Coalesced
// float4 staging into padded sT4[4][514] (conflict-free stores
// AND loads). Softmax max/sum and msg combined across the warp
// pair via tiny smem buffers.
// ============================================================
__global__ void __launch_bounds__(256) row_kernel(
    const float* __restrict__ Wf, const float* __restrict__ bf,
    const float* __restrict__ Wo, const float* __restrict__ bo,
    const float* __restrict__ lng, const float* __restrict__ lnb,
    float* __restrict__ out_alpha, float* __restrict__ out_A)
{
    __shared__ float4 sT4[4][514];         // ~32.9 KB, K then G
    __shared__ float sQ[4][16];
    __shared__ float sHL[4][16];
    __shared__ float sGG[4][16];
    __shared__ float sWf[16][17];
    __shared__ float sbf[16], sWo[16], slng[16], slnb[16];
    __shared__ float sbo;
    __shared__ float sMax[4][2], sSum[4][2];
    __shared__ float sAcc[4][16];

    int b = blockIdx.y;
    int c0 = blockIdx.x * 4;
    int t = threadIdx.x;
    int lane = t & 31, warp = t >> 5;
    int r = warp >> 1, h = warp & 1;       // row within block, half
    int c = c0 + r;

    if (t < 16) { sbf[t]=bf[t]; sWo[t]=Wo[t]; slng[t]=lng[t]; slnb[t]=lnb[t]; }
    if (t == 16) sbo = bo[0];
    if (t >= 32 && t < 48) {
        int i = t - 32;
        #pragma unroll
        for (int j = 0; j < 16; j++) sWf[i][j] = Wf[i*16+j];
    }
    if (t >= 64 && t < 128) {              // 4 rows x 16
        int rr = (t-64) >> 4, j = t & 15;
        size_t o = ((size_t)b*NC + c0 + rr)*NH + j;
        sQ[rr][j] = g_q[o]; sHL[rr][j] = g_hl[o]; sGG[rr][j] = g_gg[o];
    }
    // stage K: fully coalesced linear float4 reads
    {
        const float4* kb = (const float4*)(g_k + (size_t)b*NC*NH);
        #pragma unroll
        for (int ii = 0; ii < 8; ii++) {
            int f = t + ii*256;
            sT4[f & 3][f >> 2] = __ldg(kb + f);
        }
    }
    __syncthreads();

    float* Arow = out_A + ((size_t)b*NC + c)*NC;

    {   // ---- phase 1: sim + softmax (half row per warp) ----
        float q[16];
        #pragma unroll
        for (int j = 0; j < 16; j++) q[j] = sQ[r][j];
        float sv[8];
        #pragma unroll
        for (int i = 0; i < 8; i++) {
            int d = h*256 + i*32 + lane;
            float4 k0 = sT4[0][d], k1 = sT4[1][d], k2 = sT4[2][d], k3 = sT4[3][d];
            float dot = q[0]*k0.x + q[1]*k0.y + q[2]*k0.z + q[3]*k0.w
                      + q[4]*k1.x + q[5]*k1.y + q[6]*k1.z + q[7]*k1.w
                      + q[8]*k2.x + q[9]*k2.y + q[10]*k2.z + q[11]*k2.w
                      + q[12]*k3.x + q[13]*k3.y + q[14]*k3.z + q[15]*k3.w;
            float s = fmaxf(dot, 0.f) + 0.2f*__ldg(g_prior + (size_t)c*NC + d);
            if (d == c) s += 1.f;
            sv[i] = s;
        }
        float mx = sv[0];
        #pragma unroll
        for (int i = 1; i < 8; i++) mx = fmaxf(mx, sv[i]);
        #pragma unroll
        for (int off = 16; off; off >>= 1)
            mx = fmaxf(mx, __shfl_xor_sync(0xffffffffu, mx, off));
        if (lane == 0) sMax[r][h] = mx;
        __syncthreads();
        mx = fmaxf(sMax[r][0], sMax[r][1]);

        float sum = 0.f;
        #pragma unroll
        for (int i = 0; i < 8; i++) { sv[i] = __expf(sv[i]-mx); sum += sv[i]; }
        #pragma unroll
        for (int off = 16; off; off >>= 1)
            sum += __shfl_xor_sync(0xffffffffu, sum, off);
        if (lane == 0) sSum[r][h] = sum;
        __syncthreads();
        float inv = __frcp_rn(sSum[r][0] + sSum[r][1]);
        #pragma unroll
        for (int i = 0; i < 8; i++)
            Arow[h*256 + i*32 + lane] = sv[i]*inv;
    }
    __syncthreads();
    // stage G (reuse buffer)
    {
        const float4* gb = (const float4*)(g_gg + (size_t)b*NC*NH);
        #pragma unroll
        for (int ii = 0; ii < 8; ii++) {
            int f = t + ii*256;
            sT4[f & 3][f >> 2] = __ldg(gb + f);
        }
    }
    __syncthreads();

    {   // ---- phase 2: msg GEMV (half row) + pair-combine + epilogue ----
        float acc[16];
        #pragma unroll
        for (int j = 0; j < 16; j++) acc[j] = 0.f;
        #pragma unroll
        for (int i = 0; i < 8; i++) {
            int d = h*256 + i*32 + lane;
            float a = Arow[d];             // own prior write
            float4 g0 = sT4[0][d], g1 = sT4[1][d], g2 = sT4[2][d], g3 = sT4[3][d];
            acc[0]+=a*g0.x;  acc[1]+=a*g0.y;  acc[2]+=a*g0.z;  acc[3]+=a*g0.w;
            acc[4]+=a*g1.x;  acc[5]+=a*g1.y;  acc[6]+=a*g1.z;  acc[7]+=a*g1.w;
            acc[8]+=a*g2.x;  acc[9]+=a*g2.y;  acc[10]+=a*g2.z; acc[11]+=a*g2.w;
            acc[12]+=a*g3.x; acc[13]+=a*g3.y; acc[14]+=a*g3.z; acc[15]+=a*g3.w;
        }
        #pragma unroll
        for (int off = 16; off; off >>= 1) {
            #pragma unroll
            for (int j = 0; j < 16; j++)
                acc[j] += __shfl_xor_sync(0xffffffffu, acc[j], off);
        }
        if (h == 1 && lane == 0) {
            #pragma unroll
            for (int j = 0; j < 16; j++) sAcc[r][j] = acc[j];
        }
        __syncthreads();

        if (h == 0) {
            float hv[16], musum = 0.f;
            #pragma unroll
            for (int j = 0; j < 16; j++) {
                float msg = acc[j] + sAcc[r][j];
                float hg = sGG[r][j] + 0.3f*fmaxf(msg, 0.f);
                hv[j] = sHL[r][j] + 0.1f*hg;
                musum += hv[j];
            }
            float mu = musum*(1.f/16.f);
            float var = 0.f;
            #pragma unroll
            for (int j = 0; j < 16; j++) { float dd = hv[j]-mu; var += dd*dd; }
            var *= (1.f/16.f);
            float rinv = rsqrtf(var + 1e-5f);
            float v = 0.f;
            if (lane < 16) {
                float a2 = sbf[lane];
                #pragma unroll
                for (int j = 0; j < 16; j++) {
                    float hn = (hv[j]-mu)*rinv*slng[j] + slnb[j];
                    a2 += sWf[lane][j]*hn;
                }
                v = sWo[lane]*fmaxf(a2, 0.f);
            }
            #pragma unroll
            for (int off = 16; off; off >>= 1)
                v += __shfl_xor_sync(0xffffffffu, v, off);
            if (lane == 0)
                out_alpha[(size_t)b*NC + c] = 1.2f + 0.3f*tanhf(v + sbo);
        }
    }
}

// ============================================================
extern "C" void kernel_launch(void* const* d_in, const int* in_sizes, int n_in,
                              void* d_out, int out_size)
{
    const float* res = (const float*)d_in[0];
    const float* emb = (const float*)d_in[1];
    const float* Wl1 = (const float*)d_in[2];
    const float* bl1 = (const float*)d_in[3];
    const float* Wl2 = (const float*)d_in[4];
    const float* bl2 = (const float*)d_in[5];
    const float* Wg  = (const float*)d_in[6];
    const float* bg  = (const float*)d_in[7];
    const float* Wq  = (const float*)d_in[8];
    const float* bq  = (const float*)d_in[9];
    const float* Wk  = (const float*)d_in[10];
    const float* bk  = (const float*)d_in[11];
    const float* Wf  = (const float*)d_in[12];
    const float* bf  = (const float*)d_in[13];
    const float* Wo  = (const float*)d_in[14];
    const float* bo  = (const float*)d_in[15];
    const float* lng = (const float*)d_in[16];
    const float* lnb = (const float*)d_in[17];

    float* out       = (float*)d_out;
    float* out_alpha = out;                       // [B,1,C]
    float* out_h0    = out + NB*NC;               // [B,C,4]
    float* out_A     = out + NB*NC + NB*NC*4;     // [B,C,C]

    stats_partial<<<dim3(NS, NB), 128>>>(res);
    prior_kernel <<<NC, 128>>>(emb);
    stats_final  <<<dim3(16, NB), 128>>>(Wl1,bl1,Wl2,bl2,Wg,bg,Wq,bq,Wk,bk,out_h0);
    row_kernel   <<<dim3(NC/4, NB), 256>>>(Wf,bf,Wo,bo,lng,lnb,out_alpha,out_A);
}

// round 17
// speedup vs baseline: 1.7689x; 1.0320x over previous
#include <cuda_runtime.h>
#include <math.h>

#define NB 8
#define NL 8192
#define NC 512
#define NH 16
#define NS 256          // L-slices for stats partial reduction
#define LS (NL/NS)      // 32 rows per slice

// ---- scratch (no allocations allowed) ----
__device__ float g_part[NB*NS*3*NC];   // [b][s][comp][c]  (12.6 MB)
__device__ float g_q [NB*NC*NH];
__device__ float g_k [NB*NC*NH];
__device__ float g_gg[NB*NC*NH];       // h_graph_in
__device__ float g_hl[NB*NC*NH];       // h_local
__device__ float g_prior[NC*NC];       // relu(E E^T)  (1 MB)

// ============================================================
// Kernel 1: streaming stats over L.  grid (NS, NB), 128 threads.
// 2048 blocks -> ~56 warps/SM resident for latency hiding.
// ============================================================
__global__ void __launch_bounds__(128) stats_partial(const float* __restrict__ r) {
    int s = blockIdx.x, b = blockIdx.y;
    int t = threadIdx.x;
    const float* base = r + ((size_t)b*NL + (size_t)s*LS)*NC + t*4;
    float4 s1 = make_float4(0.f,0.f,0.f,0.f);
    float4 s2 = make_float4(0.f,0.f,0.f,0.f);
    float4 mx = make_float4(0.f,0.f,0.f,0.f);
    #pragma unroll 8
    for (int l = 0; l < LS; l++) {
        float4 v = __ldg((const float4*)(base + (size_t)l*NC));
        float ax = fabsf(v.x), ay = fabsf(v.y), az = fabsf(v.z), aw = fabsf(v.w);
        s1.x += ax; s1.y += ay; s1.z += az; s1.w += aw;
        s2.x += v.x*v.x; s2.y += v.y*v.y; s2.z += v.z*v.z; s2.w += v.w*v.w;
        mx.x = fmaxf(mx.x, ax); mx.y = fmaxf(mx.y, ay);
        mx.z = fmaxf(mx.z, az); mx.w = fmaxf(mx.w, aw);
    }
    size_t o = (size_t)((b*NS + s)*3)*NC + t*4;
    *(float4*)(g_part + o         ) = s1;
    *(float4*)(g_part + o +   NC  ) = mx;
    *(float4*)(g_part + o + 2*NC  ) = s2;
}

// ============================================================
// Kernel 2: combine partials.  grid (16, NB), 128 threads.
// 32 c per block; 4 s-groups of 64; t<32 finishes + runs MLPs.
// ============================================================
__global__ void __launch_bounds__(128) stats_final(
    const float* __restrict__ Wl1, const float* __restrict__ bl1,
    const float* __restrict__ Wl2, const float* __restrict__ bl2,
    const float* __restrict__ Wg,  const float* __restrict__ bg,
    const float* __restrict__ Wq,  const float* __restrict__ bq,
    const float* __restrict__ Wk,  const float* __restrict__ bk,
    float* __restrict__ h0_out)
{
    int b = blockIdx.y;
    int t = threadIdx.x;
    int cl = t & 31;                // c within 32-chunk
    int sg = t >> 5;                // s-group 0..3

    __shared__ float red[3][4][32];
    __shared__ float sWl1[64], sWl2[256], sWg[64], sWq[64], sWk[64];
    __shared__ float sbl1[16], sbl2[16], sbg[16], sbq[16], sbk[16];
    if (t < 64) { sWl1[t]=Wl1[t]; sWg[t]=Wg[t]; sWq[t]=Wq[t]; sWk[t]=Wk[t]; }
    if (t >= 64 && t < 80) {
        int i = t-64;
        sbl1[i]=bl1[i]; sbl2[i]=bl2[i]; sbg[i]=bg[i]; sbq[i]=bq[i]; sbk[i]=bk[i];
    }
    sWl2[t] = Wl2[t]; sWl2[t+128] = Wl2[t+128];

    int c = blockIdx.x*32 + cl;
    float s1 = 0.f, s2 = 0.f, mx = 0.f;
    #pragma unroll 8
    for (int s = sg*64; s < sg*64 + 64; s++) {
        size_t o = (size_t)((b*NS + s)*3)*NC + c;
        s1 += g_part[o];
        mx  = fmaxf(mx, g_part[o + NC]);
        s2 += g_part[o + 2*NC];
    }
    red[0][sg][cl] = s1; red[1][sg][cl] = mx; red[2][sg][cl] = s2;
    __syncthreads();

    if (t < 32) {
        s1 = (red[0][0][cl] + red[0][1][cl]) + (red[0][2][cl] + red[0][3][cl]);
        mx = fmaxf(fmaxf(red[1][0][cl], red[1][1][cl]),
                   fmaxf(red[1][2][cl], red[1][3][cl]));
        s2 = (red[2][0][cl] + red[2][1][cl]) + (red[2][2][cl] + red[2][3][cl]);

        float m  = s1 * (1.f/NL);
        float sq = s2 * (1.f/NL);
        float sd = sqrtf(fmaxf(sq - m*m, 0.f));
        float h0[4] = { m, mx, sd, sq };
        *(float4*)(h0_out + ((size_t)b*NC + c)*4) = make_float4(m, mx, sd, sq);

        float hid[16];
        #pragma unroll
        for (int i = 0; i < 16; i++) {
            float a = sbl1[i];
            #pragma unroll
            for (int j = 0; j < 4; j++) a += sWl1[i*4+j]*h0[j];
            hid[i] = fmaxf(a, 0.f);
        }
        size_t ofs = ((size_t)b*NC + c)*NH;
        #pragma unroll
        for (int i = 0; i < 16; i++) {
            float a = sbl2[i];
            #pragma unroll
            for (int j = 0; j < 16; j++) a += sWl2[i*16+j]*hid[j];
            g_hl[ofs+i] = a;
            float qv = sbq[i], kv = sbk[i], gv = sbg[i];
            #pragma unroll
            for (int j = 0; j < 4; j++) {
                qv += sWq[i*4+j]*h0[j];
                kv += sWk[i*4+j]*h0[j];
                gv += sWg[i*4+j]*h0[j];
            }
            g_q[ofs+i] = qv; g_k[ofs+i] = kv; g_gg[ofs+i] = gv;
        }
    }
}

// ============================================================
// Kernel 3: sim_prior = relu(E E^T).  grid (NC), 128 threads.
// ============================================================
__global__ void __launch_bounds__(128) prior_kernel(const float* __restrict__ E) {
    int c = blockIdx.x;
    __shared__ float ec[16];
    if (threadIdx.x < 16) ec[threadIdx.x] = E[c*16 + threadIdx.x];
    __syncthreads();
    for (int d = threadIdx.x; d < NC; d += blockDim.x) {
        const float* ed = E + d*16;
        float s = 0.f;
        #pragma unroll
        for (int j = 0; j < 16; j++) s += ec[j]*ed[j];
        g_prior[(size_t)c*NC + d] = fmaxf(s, 0.f);
    }
}

// ============================================================
// Kernel 4: grid (NC/4, NB), 256 threads (8 warps), 4 rows per
// block, TWO warps per row. Coalesced float4 staging into padded
// sT4[4][514]. Normalized softmax weights kept in sv[8] REGISTERS
// across the G restage (no gmem A re-read in phase 2).
// ============================================================
__global__ void __launch_bounds__(256) row_kernel(
    const float* __restrict__ Wf, const float* __restrict__ bf,
    const float* __restrict__ Wo, const float* __restrict__ bo,
    const float* __restrict__ lng, const float* __restrict__ lnb,
    float* __restrict__ out_alpha, float* __restrict__ out_A)
{
    __shared__ float4 sT4[4][514];         // ~32.9 KB, K then G
    __shared__ float sQ[4][16];
    __shared__ float sHL[4][16];
    __shared__ float sGG[4][16];
    __shared__ float sWf[16][17];
    __shared__ float sbf[16], sWo[16], slng[16], slnb[16];
    __shared__ float sbo;
    __shared__ float sMax[4][2], sSum[4][2];
    __shared__ float sAcc[4][16];

    int b = blockIdx.y;
    int c0 = blockIdx.x * 4;
    int t = threadIdx.x;
    int lane = t & 31, warp = t >> 5;
    int r = warp >> 1, h = warp & 1;       // row within block, half
    int c = c0 + r;

    if (t < 16) { sbf[t]=bf[t]; sWo[t]=Wo[t]; slng[t]=lng[t]; slnb[t]=lnb[t]; }
    if (t == 16) sbo = bo[0];
    if (t >= 32 && t < 48) {
        int i = t - 32;
        #pragma unroll
        for (int j = 0; j < 16; j++) sWf[i][j] = Wf[i*16+j];
    }
    if (t >= 64 && t < 128) {              // 4 rows x 16
        int rr = (t-64) >> 4, j = t & 15;
        size_t o = ((size_t)b*NC + c0 + rr)*NH + j;
        sQ[rr][j] = g_q[o]; sHL[rr][j] = g_hl[o]; sGG[rr][j] = g_gg[o];
    }
    // stage K: fully coalesced linear float4 reads
    {
        const float4* kb = (const float4*)(g_k + (size_t)b*NC*NH);
        #pragma unroll
        for (int ii = 0; ii < 8; ii++) {
            int f = t + ii*256;
            sT4[f & 3][f >> 2] = __ldg(kb + f);
        }
    }
    __syncthreads();

    float* Arow = out_A + ((size_t)b*NC + c)*NC;
    float sv[8];                            // lives across restage (8 regs)

    {   // ---- phase 1: sim + softmax (half row per warp) ----
        float q[16];
        #pragma unroll
        for (int j = 0; j < 16; j++) q[j] = sQ[r][j];
        #pragma unroll
        for (int i = 0; i < 8; i++) {
            int d = h*256 + i*32 + lane;
            float4 k0 = sT4[0][d], k1 = sT4[1][d], k2 = sT4[2][d], k3 = sT4[3][d];
            float dot = q[0]*k0.x + q[1]*k0.y + q[2]*k0.z + q[3]*k0.w
                      + q[4]*k1.x + q[5]*k1.y + q[6]*k1.z + q[7]*k1.w
                      + q[8]*k2.x + q[9]*k2.y + q[10]*k2.z + q[11]*k2.w
                      + q[12]*k3.x + q[13]*k3.y + q[14]*k3.z + q[15]*k3.w;
            float s = fmaxf(dot, 0.f) + 0.2f*__ldg(g_prior + (size_t)c*NC + d);
            if (d == c) s += 1.f;
            sv[i] = s;
        }
        float mx = sv[0];
        #pragma unroll
        for (int i = 1; i < 8; i++) mx = fmaxf(mx, sv[i]);
        #pragma unroll
        for (int off = 16; off; off >>= 1)
            mx = fmaxf(mx, __shfl_xor_sync(0xffffffffu, mx, off));
        if (lane == 0) sMax[r][h] = mx;
        __syncthreads();
        mx = fmaxf(sMax[r][0], sMax[r][1]);

        float sum = 0.f;
        #pragma unroll
        for (int i = 0; i < 8; i++) { sv[i] = __expf(sv[i]-mx); sum += sv[i]; }
        #pragma unroll
        for (int off = 16; off; off >>= 1)
            sum += __shfl_xor_sync(0xffffffffu, sum, off);
        if (lane == 0) sSum[r][h] = sum;
        __syncthreads();
        float inv = __frcp_rn(sSum[r][0] + sSum[r][1]);
        #pragma unroll
        for (int i = 0; i < 8; i++) {
            sv[i] *= inv;                  // keep normalized weight in regs
            Arow[h*256 + i*32 + lane] = sv[i];
        }
    }
    __syncthreads();
    // stage G (reuse buffer)
    {
        const float4* gb = (const float4*)(g_gg + (size_t)b*NC*NH);
        #pragma unroll
        for (int ii = 0; ii < 8; ii++) {
            int f = t + ii*256;
            sT4[f & 3][f >> 2] = __ldg(gb + f);
        }
    }
    __syncthreads();

    {   // ---- phase 2: msg GEMV (weights from registers) + epilogue ----
        float acc[16];
        #pragma unroll
        for (int j = 0; j < 16; j++) acc[j] = 0.f;
        #pragma unroll
        for (int i = 0; i < 8; i++) {
            int d = h*256 + i*32 + lane;
            float a = sv[i];
            float4 g0 = sT4[0][d], g1 = sT4[1][d], g2 = sT4[2][d], g3 = sT4[3][d];
            acc[0]+=a*g0.x;  acc[1]+=a*g0.y;  acc[2]+=a*g0.z;  acc[3]+=a*g0.w;
            acc[4]+=a*g1.x;  acc[5]+=a*g1.y;  acc[6]+=a*g1.z;  acc[7]+=a*g1.w;
            acc[8]+=a*g2.x;  acc[9]+=a*g2.y;  acc[10]+=a*g2.z; acc[11]+=a*g2.w;
            acc[12]+=a*g3.x; acc[13]+=a*g3.y; acc[14]+=a*g3.z; acc[15]+=a*g3.w;
        }
        #pragma unroll
        for (int off = 16; off; off >>= 1) {
            #pragma unroll
            for (int j = 0; j < 16; j++)
                acc[j] += __shfl_xor_sync(0xffffffffu, acc[j], off);
        }
        if (h == 1 && lane == 0) {
            #pragma unroll
            for (int j = 0; j < 16; j++) sAcc[r][j] = acc[j];
        }
        __syncthreads();

        if (h == 0) {
            float hv[16], musum = 0.f;
            #pragma unroll
            for (int j = 0; j < 16; j++) {
                float msg = acc[j] + sAcc[r][j];
                float hg = sGG[r][j] + 0.3f*fmaxf(msg, 0.f);
                hv[j] = sHL[r][j] + 0.1f*hg;
                musum += hv[j];
            }
            float mu = musum*(1.f/16.f);
            float var = 0.f;
            #pragma unroll
            for (int j = 0; j < 16; j++) { float dd = hv[j]-mu; var += dd*dd; }
            var *= (1.f/16.f);
            float rinv = rsqrtf(var + 1e-5f);
            float v = 0.f;
            if (lane < 16) {
                float a2 = sbf[lane];
                #pragma unroll
                for (int j = 0; j < 16; j++) {
                    float hn = (hv[j]-mu)*rinv*slng[j] + slnb[j];
                    a2 += sWf[lane][j]*hn;
                }
                v = sWo[lane]*fmaxf(a2, 0.f);
            }
            #pragma unroll
            for (int off = 16; off; off >>= 1)
                v += __shfl_xor_sync(0xffffffffu, v, off);
            if (lane == 0)
                out_alpha[(size_t)b*NC + c] = 1.2f + 0.3f*tanhf(v + sbo);
        }
    }
}

// ============================================================
extern "C" void kernel_launch(void* const* d_in, const int* in_sizes, int n_in,
                              void* d_out, int out_size)
{
    const float* res = (const float*)d_in[0];
    const float* emb = (const float*)d_in[1];
    const float* Wl1 = (const float*)d_in[2];
    const float* bl1 = (const float*)d_in[3];
    const float* Wl2 = (const float*)d_in[4];
    const float* bl2 = (const float*)d_in[5];
    const float* Wg  = (const float*)d_in[6];
    const float* bg  = (const float*)d_in[7];
    const float* Wq  = (const float*)d_in[8];
    const float* bq  = (const float*)d_in[9];
    const float* Wk  = (const float*)d_in[10];
    const float* bk  = (const float*)d_in[11];
    const float* Wf  = (const float*)d_in[12];
    const float* bf  = (const float*)d_in[13];
    const float* Wo  = (const float*)d_in[14];
    const float* bo  = (const float*)d_in[15];
    const float* lng = (const float*)d_in[16];
    const float* lnb = (const float*)d_in[17];

    float* out       = (float*)d_out;
    float* out_alpha = out;                       // [B,1,C]
    float* out_h0    = out + NB*NC;               // [B,C,4]
    float* out_A     = out + NB*NC + NB*NC*4;     // [B,C,C]

    stats_partial<<<dim3(NS, NB), 128>>>(res);
    prior_kernel <<<NC, 128>>>(emb);
    stats_final  <<<dim3(16, NB), 128>>>(Wl1,bl1,Wl2,bl2,Wg,bg,Wq,bq,Wk,bk,out_h0);
    row_kernel   <<<dim3(NC/4, NB), 256>>>(Wf,bf,Wo,bo,lng,lnb,out_alpha,out_A);
}